// round 8
// baseline (speedup 1.0000x reference)
#include <cuda_runtime.h>
#include <cuda_bf16.h>
#include <cstdint>
#include <math.h>

#define BB 4
#define NN 16384
#define CC 256
#define HH 8
#define KK 64
#define DD 32
#define BNTOT (BB*NN)

// ---------------- scratch ----------------
__device__ float g_S[BB*KK*CC];
__device__ float g_denom[BB*KK];
__device__ float g_bias[BNTOT*KK];
__device__ __nv_bfloat16 g_Xhi[BNTOT*CC], g_Xlo[BNTOT*CC];
__device__ __nv_bfloat16 g_Ahi[BNTOT*KK], g_Alo[BNTOT*KK];
__device__ __nv_bfloat16 g_qhi[BNTOT*CC], g_qlo[BNTOT*CC];
__device__ __nv_bfloat16 g_xhi[BNTOT*CC], g_xlo[BNTOT*CC];
__device__ __nv_bfloat16 g_Wqt_hi[CC*CC], g_Wqt_lo[CC*CC];
__device__ __nv_bfloat16 g_Wpt_hi[CC*CC], g_Wpt_lo[CC*CC];
__device__ __nv_bfloat16 g_kchi[BB*HH*KK*DD], g_kclo[BB*HH*KK*DD];   // scaled, [b][h][cl][d]
__device__ __nv_bfloat16 g_vcThi[BB*HH*DD*KK], g_vcTlo[BB*HH*DD*KK]; // [b][h][d][cl]

// ---------------- helpers ----------------
__device__ __forceinline__ uint32_t smem_u32(const void* p) {
    uint32_t a;
    asm("{ .reg .u64 t; cvta.to.shared.u64 t, %1; cvt.u32.u64 %0, t; }" : "=r"(a) : "l"(p));
    return a;
}
#define CP16(dst, src) \
    asm volatile("cp.async.cg.shared.global [%0], [%1], 16;" :: "r"(dst), "l"(src))
#define CPCOMMIT() asm volatile("cp.async.commit_group;" ::: "memory")
#define CPWAIT(n)  asm volatile("cp.async.wait_group %0;" :: "n"(n) : "memory")

__device__ __forceinline__ void ldsm_x4(uint32_t* r, uint32_t addr) {
    asm volatile("ldmatrix.sync.aligned.m8n8.x4.shared.b16 {%0,%1,%2,%3}, [%4];"
                 : "=r"(r[0]), "=r"(r[1]), "=r"(r[2]), "=r"(r[3]) : "r"(addr));
}
__device__ __forceinline__ void ldsm_x4_t(uint32_t* r, uint32_t addr) {
    asm volatile("ldmatrix.sync.aligned.m8n8.x4.trans.shared.b16 {%0,%1,%2,%3}, [%4];"
                 : "=r"(r[0]), "=r"(r[1]), "=r"(r[2]), "=r"(r[3]) : "r"(addr));
}
__device__ __forceinline__ void mma_bf16(float* d, const uint32_t* a,
                                         uint32_t b0, uint32_t b1) {
    asm volatile(
        "mma.sync.aligned.m16n8k16.row.col.f32.bf16.bf16.f32 "
        "{%0,%1,%2,%3}, {%4,%5,%6,%7}, {%8,%9}, {%0,%1,%2,%3};"
        : "+f"(d[0]), "+f"(d[1]), "+f"(d[2]), "+f"(d[3])
        : "r"(a[0]), "r"(a[1]), "r"(a[2]), "r"(a[3]), "r"(b0), "r"(b1));
}
__device__ __forceinline__ void pack_split(float a, float b, uint32_t& hi, uint32_t& lo) {
    __nv_bfloat16 ah = __float2bfloat16(a), bh = __float2bfloat16(b);
    __nv_bfloat16 al = __float2bfloat16(a - __bfloat162float(ah));
    __nv_bfloat16 bl = __float2bfloat16(b - __bfloat162float(bh));
    __nv_bfloat162 hp; hp.x = ah; hp.y = bh;
    __nv_bfloat162 lp; lp.x = al; lp.y = bl;
    hi = *(uint32_t*)&hp; lo = *(uint32_t*)&lp;
}

// ---------------- zero accumulators ----------------
__global__ void zero_kernel() {
    int i = blockIdx.x * blockDim.x + threadIdx.x;
    if (i < BB*KK*CC) g_S[i] = 0.0f;
    if (i < BB*KK)    g_denom[i] = 0.0f;
}

// ---------------- splits ----------------
__global__ __launch_bounds__(256) void convertX_kernel(const float* __restrict__ X) {
    size_t i = ((size_t)blockIdx.x * 256 + threadIdx.x) * 8;
    float4 a = *(const float4*)(X + i);
    float4 b = *(const float4*)(X + i + 4);
    float v[8] = {a.x, a.y, a.z, a.w, b.x, b.y, b.z, b.w};
    __nv_bfloat16 h[8], l[8];
#pragma unroll
    for (int j = 0; j < 8; j++) {
        h[j] = __float2bfloat16(v[j]);
        l[j] = __float2bfloat16(v[j] - __bfloat162float(h[j]));
    }
    *(uint4*)&g_Xhi[i] = *(const uint4*)h;
    *(uint4*)&g_Xlo[i] = *(const uint4*)l;
}
__global__ __launch_bounds__(256) void convertA_kernel(const float* __restrict__ Ag) {
    size_t i = ((size_t)blockIdx.x * 256 + threadIdx.x) * 8;
    float4 a = *(const float4*)(Ag + i);
    float4 b = *(const float4*)(Ag + i + 4);
    float v[8] = {a.x, a.y, a.z, a.w, b.x, b.y, b.z, b.w};
    __nv_bfloat16 h[8], l[8];
#pragma unroll
    for (int j = 0; j < 8; j++) {
        h[j] = __float2bfloat16(v[j]);
        l[j] = __float2bfloat16(v[j] - __bfloat162float(h[j]));
    }
    *(uint4*)&g_Ahi[i] = *(const uint4*)h;
    *(uint4*)&g_Alo[i] = *(const uint4*)l;
}

// ---------------- transposed bf16 hi/lo weights ----------------
__global__ __launch_bounds__(256) void prepW_kernel(const float* __restrict__ wqkv,
                                                    const float* __restrict__ wproj) {
    int n = blockIdx.x, k = threadIdx.x;
    float wq = wqkv[k * (3*CC) + n];
    float wp = wproj[k * CC + n];
    __nv_bfloat16 qh = __float2bfloat16(wq);
    __nv_bfloat16 ph = __float2bfloat16(wp);
    int o = n * CC + k;
    g_Wqt_hi[o] = qh;
    g_Wqt_lo[o] = __float2bfloat16(wq - __bfloat162float(qh));
    g_Wpt_hi[o] = ph;
    g_Wpt_lo[o] = __float2bfloat16(wp - __bfloat162float(ph));
}

// ---------------- exact fp32 denom ----------------
__global__ __launch_bounds__(256) void denom_kernel(const float* __restrict__ Ag) {
    __shared__ float red[4][64];
    int blk = blockIdx.x;
    int b = blk >> 4, seg = blk & 15;
    int k = threadIdx.x & 63, rr = threadIdx.x >> 6;
    float s = 0.0f;
    size_t base = (size_t)b * NN + seg * 1024;
#pragma unroll 4
    for (int i = 0; i < 256; i++) s += Ag[(base + rr + i * 4) * KK + k];
    red[rr][k] = s;
    __syncthreads();
    if (threadIdx.x < 64)
        atomicAdd(&g_denom[b * KK + threadIdx.x],
                  red[0][threadIdx.x] + red[1][threadIdx.x] +
                  red[2][threadIdx.x] + red[3][threadIdx.x]);
}

// ---------------- bias = A @ cluster_bias ----------------
__global__ __launch_bounds__(256) void bias_kernel(const float* __restrict__ Ag,
                                                   const float* __restrict__ cb) {
    __shared__ float cb_s[KK*KK];
    int tid = threadIdx.x;
    {
        const float4* cb4 = (const float4*)cb;
        float4* cbs4 = (float4*)cb_s;
        for (int i = tid; i < KK*KK/4; i += 256) cbs4[i] = cb4[i];
    }
    __syncthreads();
    size_t n = (size_t)blockIdx.x * 256 + tid;
    float biasr[64];
#pragma unroll
    for (int l = 0; l < 64; l++) biasr[l] = 0.0f;
    const float4* arow = (const float4*)(Ag + n * KK);
#pragma unroll
    for (int k4 = 0; k4 < 16; k4++) {
        float4 a4 = arow[k4];
        float avv[4] = {a4.x, a4.y, a4.z, a4.w};
#pragma unroll
        for (int kk = 0; kk < 4; kk++) {
            const float4* cbr = (const float4*)(cb_s + (k4 * 4 + kk) * 64);
#pragma unroll
            for (int l4 = 0; l4 < 16; l4++) {
                float4 c4 = cbr[l4];
                biasr[l4*4+0] += avv[kk] * c4.x;
                biasr[l4*4+1] += avv[kk] * c4.y;
                biasr[l4*4+2] += avv[kk] * c4.z;
                biasr[l4*4+3] += avv[kk] * c4.w;
            }
        }
    }
    float4* dst = (float4*)(g_bias + n * KK);
#pragma unroll
    for (int l4 = 0; l4 < 16; l4++)
        dst[l4] = make_float4(biasr[l4*4], biasr[l4*4+1], biasr[l4*4+2], biasr[l4*4+3]);
}

// ---------------- tensor-core pooling (unchanged) ----------------
#define PX_ST 264
#define PA_ST 72
#define PX_SIZE (64*PX_ST)
#define PA_SIZE (64*PA_ST)
#define POOL_SMEM ((3*PX_SIZE + 3*PA_SIZE)*2)
__global__ __launch_bounds__(256, 1) void pool_tc_kernel() {
    extern __shared__ __nv_bfloat16 ps[];
    uint32_t sb = smem_u32(ps);
    int tid = threadIdx.x, lane = tid & 31, w = tid >> 5;
    int wm = w >> 2, wn = w & 3;
    int b = blockIdx.x >> 5;
    int nbase = (blockIdx.x & 31) * 512;
    const __nv_bfloat16* Asrc[3] = {g_Ahi, g_Ahi, g_Alo};
    const __nv_bfloat16* Xsrc[3] = {g_Xhi, g_Xlo, g_Xhi};

    float acc[2][8][4];
#pragma unroll
    for (int i = 0; i < 2; i++)
#pragma unroll
        for (int j = 0; j < 8; j++)
#pragma unroll
            for (int r = 0; r < 4; r++) acc[i][j][r] = 0.0f;

    auto issue = [&](int c) {
        int s = c >> 3, kc_ = c & 7, buf = c % 3;
        size_t grow0 = (size_t)b * NN + nbase + kc_ * 64;
#pragma unroll
        for (int i = 0; i < 8; i++) {
            int idx = tid + i * 256;
            int row = idx >> 5, ch = idx & 31;
            CP16(sb + (uint32_t)(buf * PX_SIZE + row * PX_ST + ch * 8) * 2,
                 Xsrc[s] + (grow0 + row) * CC + ch * 8);
        }
#pragma unroll
        for (int i = 0; i < 2; i++) {
            int idx = tid + i * 256;
            int row = idx >> 3, ch = idx & 7;
            CP16(sb + (uint32_t)(3 * PX_SIZE + buf * PA_SIZE + row * PA_ST + ch * 8) * 2,
                 Asrc[s] + (grow0 + row) * KK + ch * 8);
        }
        CPCOMMIT();
    };

    issue(0); issue(1);
#pragma unroll 1
    for (int c = 0; c < 24; c++) {
        if (c < 22) { CPWAIT(1); } else { CPWAIT(0); }
        __syncthreads();
        if (c + 2 < 24) issue(c + 2);
        int buf = c % 3;
        uint32_t xb = sb + (uint32_t)(buf * PX_SIZE) * 2;
        uint32_t ab = sb + (uint32_t)(3 * PX_SIZE + buf * PA_SIZE) * 2;
#pragma unroll
        for (int kt = 0; kt < 4; kt++) {
            uint32_t af[2][4];
#pragma unroll
            for (int mt = 0; mt < 2; mt++) {
                uint32_t r[4];
                ldsm_x4_t(r, ab + (uint32_t)((kt * 16 + (lane & 15)) * PA_ST +
                                             wm * 32 + mt * 16 + (lane >> 4) * 8) * 2);
                af[mt][0] = r[0]; af[mt][1] = r[2]; af[mt][2] = r[1]; af[mt][3] = r[3];
            }
#pragma unroll
            for (int nb = 0; nb < 4; nb++) {
                uint32_t bfr[4];
                ldsm_x4_t(bfr, xb + (uint32_t)((kt * 16 + (lane & 15)) * PX_ST +
                                               wn * 64 + nb * 16 + (lane >> 4) * 8) * 2);
#pragma unroll
                for (int mt = 0; mt < 2; mt++) {
                    mma_bf16(acc[mt][nb*2],   af[mt], bfr[0], bfr[1]);
                    mma_bf16(acc[mt][nb*2+1], af[mt], bfr[2], bfr[3]);
                }
            }
        }
    }
#pragma unroll
    for (int mt = 0; mt < 2; mt++)
#pragma unroll
        for (int nt = 0; nt < 8; nt++) {
            int cl = wm * 32 + mt * 16 + (lane >> 2);
            int col = wn * 64 + nt * 8 + 2 * (lane & 3);
            float* d0 = &g_S[(b * KK + cl) * CC + col];
            atomicAdd(d0,     acc[mt][nt][0]);
            atomicAdd(d0 + 1, acc[mt][nt][1]);
            float* d1 = &g_S[(b * KK + cl + 8) * CC + col];
            atomicAdd(d1,     acc[mt][nt][2]);
            atomicAdd(d1 + 1, acc[mt][nt][3]);
        }
}

// ---------------- kc/vc from S -> scaled bf16 splits + transposed vc ----------------
__global__ __launch_bounds__(256) void kcvc_kernel(const float* __restrict__ wqkv) {
    int bk = blockIdx.x;
    int b = bk >> 6;
    int k = bk & 63;
    int t = threadIdx.x;
    __shared__ float s_row[CC];
    s_row[t] = g_S[bk * CC + t];
    __syncthreads();
    float inv = 1.0f / (g_denom[bk] + 1e-8f);
    float ak = 0.0f, av = 0.0f;
#pragma unroll 8
    for (int c = 0; c < CC; c++) {
        float s = s_row[c];
        ak += s * wqkv[c * (3*CC) + CC  + t];
        av += s * wqkv[c * (3*CC) + 2*CC + t];
    }
    int h = t >> 5, dd = t & 31;
    const float SC = 0.17677669529663689f;
    float kcv = ak * inv * SC;
    float vcv = av * inv;
    size_t ok = ((size_t)(b * HH + h) * KK + k) * DD + dd;
    size_t ov = ((size_t)(b * HH + h) * DD + dd) * KK + k;
    __nv_bfloat16 kh = __float2bfloat16(kcv);
    __nv_bfloat16 vh = __float2bfloat16(vcv);
    g_kchi[ok] = kh;  g_kclo[ok] = __float2bfloat16(kcv - __bfloat162float(kh));
    g_vcThi[ov] = vh; g_vcTlo[ov] = __float2bfloat16(vcv - __bfloat162float(vh));
}

// ---------------- HMMA bf16 3-split GEMM, K=64 chunks (12 stages) ----------------
#define AST 72
#define STAGE_ELE (128 * AST)
#define GEMM_SMEM_BYTES (2 * 3 * STAGE_ELE * 2)    // 110592 B
__global__ __launch_bounds__(256, 2) void gemm_bf16x3_mma(
    const __nv_bfloat16* __restrict__ Ahi, const __nv_bfloat16* __restrict__ Alo,
    const __nv_bfloat16* __restrict__ Whi, const __nv_bfloat16* __restrict__ Wlo,
    const float* __restrict__ bias, float* __restrict__ Cout,
    __nv_bfloat16* __restrict__ Ohi, __nv_bfloat16* __restrict__ Olo) {
    extern __shared__ __nv_bfloat16 smemb[];
    __nv_bfloat16* As = smemb;
    __nv_bfloat16* Bs = smemb + 3 * STAGE_ELE;
    uint32_t a_sm = smem_u32(As);
    uint32_t b_sm = smem_u32(Bs);

    int tid = threadIdx.x;
    int lane = tid & 31, w = tid >> 5;
    int wr = w >> 2, wc = w & 3;
    size_t mbase = (size_t)blockIdx.x * 128;
    int nbase = blockIdx.y * 128;

    const __nv_bfloat16* Asp[3] = {Ahi, Ahi, Alo};
    const __nv_bfloat16* Wsp[3] = {Whi, Wlo, Whi};

    int ldrow = tid >> 1;            // 0..127
    int ldcw  = (tid & 1) * 4;       // 16B-word offset (0 or 4)

    float acc[4][4][4];
#pragma unroll
    for (int i = 0; i < 4; i++)
#pragma unroll
        for (int j = 0; j < 4; j++)
#pragma unroll
            for (int r = 0; r < 4; r++) acc[i][j][r] = 0.0f;

    auto issue = [&](int c) {
        int s = c >> 2;              // split product 0..2
        int ko = (c & 3) * 64;       // K offset within 256
        const __nv_bfloat16* Ap = Asp[s];
        const __nv_bfloat16* Wp = Wsp[s];
        uint32_t sa = a_sm + (uint32_t)((c % 3) * STAGE_ELE) * 2;
        uint32_t sb = b_sm + (uint32_t)((c % 3) * STAGE_ELE) * 2;
#pragma unroll
        for (int t = 0; t < 4; t++) {
            int cw = ldcw + t;
            CP16(sa + (uint32_t)(ldrow * AST + cw * 8) * 2,
                 Ap + (mbase + ldrow) * CC + ko + cw * 8);
            CP16(sb + (uint32_t)(ldrow * AST + cw * 8) * 2,
                 Wp + (size_t)(nbase + ldrow) * CC + ko + cw * 8);
        }
        CPCOMMIT();
    };

    int arow = (lane & 7) + 8 * ((lane >> 3) & 1);
    int akw  = (lane >> 4) * 8;
    int brow = (lane & 7) + 8 * ((lane >> 4) & 1);
    int bkw  = ((lane >> 3) & 1) * 8;

    auto compute = [&](int stage) {
        uint32_t sa = a_sm + (uint32_t)(stage * STAGE_ELE) * 2;
        uint32_t sb = b_sm + (uint32_t)(stage * STAGE_ELE) * 2;
#pragma unroll
        for (int ks = 0; ks < 64; ks += 16) {
            uint32_t afr[4][4];
#pragma unroll
            for (int mt = 0; mt < 4; mt++)
                ldsm_x4(afr[mt], sa + (uint32_t)(((wr * 64 + mt * 16 + arow) * AST) + ks + akw) * 2);
            uint32_t bfr[2][4];
#pragma unroll
            for (int nt2 = 0; nt2 < 2; nt2++)
                ldsm_x4(bfr[nt2], sb + (uint32_t)(((wc * 32 + nt2 * 16 + brow) * AST) + ks + bkw) * 2);
#pragma unroll
            for (int mt = 0; mt < 4; mt++)
#pragma unroll
                for (int nt = 0; nt < 4; nt++)
                    mma_bf16(acc[mt][nt], afr[mt],
                             bfr[nt >> 1][(nt & 1) * 2],
                             bfr[nt >> 1][(nt & 1) * 2 + 1]);
        }
    };

    issue(0);
    issue(1);
#pragma unroll 1
    for (int c = 0; c < 12; c++) {
        if (c < 10) { CPWAIT(1); } else { CPWAIT(0); }
        __syncthreads();
        if (c + 2 < 12) issue(c + 2);
        compute(c % 3);
    }

    int g = lane >> 2, ti = lane & 3;
#pragma unroll
    for (int mt = 0; mt < 4; mt++) {
#pragma unroll
        for (int nt = 0; nt < 4; nt++) {
            size_t row = mbase + wr * 64 + mt * 16 + g;
            int col = nbase + wc * 32 + nt * 8 + ti * 2;
            if (Cout) {
                float bx = 0.0f, by = 0.0f;
                if (bias) { bx = bias[col]; by = bias[col + 1]; }
                float2 v0, v1;
                v0.x = acc[mt][nt][0] + bx; v0.y = acc[mt][nt][1] + by;
                v1.x = acc[mt][nt][2] + bx; v1.y = acc[mt][nt][3] + by;
                *(float2*)&Cout[row * CC + col] = v0;
                *(float2*)&Cout[(row + 8) * CC + col] = v1;
            } else {
                uint32_t h0, l0, h1, l1;
                pack_split(acc[mt][nt][0], acc[mt][nt][1], h0, l0);
                pack_split(acc[mt][nt][2], acc[mt][nt][3], h1, l1);
                *(uint32_t*)&Ohi[row * CC + col] = h0;
                *(uint32_t*)&Olo[row * CC + col] = l0;
                *(uint32_t*)&Ohi[(row + 8) * CC + col] = h1;
                *(uint32_t*)&Olo[(row + 8) * CC + col] = l1;
            }
        }
    }
}

// ---------------- tensor-core attention (2 CTAs/SM; bias reloaded per head) -------------
#define ATT_BUF_BYTES 19456
#define ATT_SMEM_BYTES (2 * ATT_BUF_BYTES)
__global__ __launch_bounds__(256, 2) void attn_tc_kernel() {
    extern __shared__ __nv_bfloat16 smn[];
    uint32_t sb = smem_u32(smn);
    int tid = threadIdx.x, lane = tid & 31, w = tid >> 5;
    size_t tok0 = (size_t)blockIdx.x * 128;
    int b = blockIdx.x >> 7;
    int r = lane >> 2, c = lane & 3;
    size_t trow0 = tok0 + (size_t)w * 16 + r;
    size_t trow1 = trow0 + 8;

    const uint32_t KHI = 0, KLO = 5120, VHI = 10240, VLO = 14848;

    auto issue_head = [&](int h) {
        uint32_t bo = (uint32_t)(h & 1) * ATT_BUF_BYTES;
        {
            int rr = tid >> 2, cc = tid & 3;
            size_t src = ((size_t)(b * HH + h) * KK + rr) * DD + cc * 8;
            uint32_t d = (uint32_t)(rr * 40 + cc * 8) * 2;
            CP16(sb + bo + KHI + d, g_kchi + src);
            CP16(sb + bo + KLO + d, g_kclo + src);
        }
        {
            int rr = tid >> 3, cc = tid & 7;
            size_t src = ((size_t)(b * HH + h) * DD + rr) * KK + cc * 8;
            uint32_t d = (uint32_t)(rr * 72 + cc * 8) * 2;
            CP16(sb + bo + VHI + d, g_vcThi + src);
            CP16(sb + bo + VLO + d, g_vcTlo + src);
        }
        CPCOMMIT();
    };
    issue_head(0);

    int brow = (lane & 7) + 8 * ((lane >> 4) & 1);
    int bkw  = ((lane >> 3) & 1) * 8;

#pragma unroll 1
    for (int h = 0; h < HH; h++) {
        CPWAIT(0);
        __syncthreads();
        if (h + 1 < HH) issue_head(h + 1);
        uint32_t bo = (uint32_t)(h & 1) * ATT_BUF_BYTES;

        // Q fragments direct from global
        uint32_t qhi[2][4], qlo[2][4];
#pragma unroll
        for (int ks = 0; ks < 2; ks++) {
            size_t col = (size_t)h * DD + ks * 16 + c * 2;
            qhi[ks][0] = *(const uint32_t*)(g_qhi + trow0 * CC + col);
            qhi[ks][1] = *(const uint32_t*)(g_qhi + trow1 * CC + col);
            qhi[ks][2] = *(const uint32_t*)(g_qhi + trow0 * CC + col + 8);
            qhi[ks][3] = *(const uint32_t*)(g_qhi + trow1 * CC + col + 8);
            qlo[ks][0] = *(const uint32_t*)(g_qlo + trow0 * CC + col);
            qlo[ks][1] = *(const uint32_t*)(g_qlo + trow1 * CC + col);
            qlo[ks][2] = *(const uint32_t*)(g_qlo + trow0 * CC + col + 8);
            qlo[ks][3] = *(const uint32_t*)(g_qlo + trow1 * CC + col + 8);
        }

        // logits init with bias rows (L2-resident after head 0)
        float L[8][4];
#pragma unroll
        for (int t = 0; t < 8; t++) {
            float2 b0 = *(const float2*)(g_bias + trow0 * KK + t * 8 + c * 2);
            float2 b1 = *(const float2*)(g_bias + trow1 * KK + t * 8 + c * 2);
            L[t][0] = b0.x; L[t][1] = b0.y;
            L[t][2] = b1.x; L[t][3] = b1.y;
        }
#pragma unroll
        for (int g2 = 0; g2 < 4; g2++) {
#pragma unroll
            for (int ks = 0; ks < 2; ks++) {
                uint32_t bh[4], bl[4];
                uint32_t ad = (uint32_t)((g2 * 16 + brow) * 40 + ks * 16 + bkw) * 2;
                ldsm_x4(bh, sb + bo + KHI + ad);
                ldsm_x4(bl, sb + bo + KLO + ad);
                mma_bf16(L[2*g2],   qhi[ks], bh[0], bh[1]);
                mma_bf16(L[2*g2],   qhi[ks], bl[0], bl[1]);
                mma_bf16(L[2*g2],   qlo[ks], bh[0], bh[1]);
                mma_bf16(L[2*g2+1], qhi[ks], bh[2], bh[3]);
                mma_bf16(L[2*g2+1], qhi[ks], bl[2], bl[3]);
                mma_bf16(L[2*g2+1], qlo[ks], bh[2], bh[3]);
            }
        }

        // softmax (rows r, r+8) via quad shuffles
        float m0 = -1e30f, m1 = -1e30f;
#pragma unroll
        for (int t = 0; t < 8; t++) {
            m0 = fmaxf(m0, fmaxf(L[t][0], L[t][1]));
            m1 = fmaxf(m1, fmaxf(L[t][2], L[t][3]));
        }
        m0 = fmaxf(m0, __shfl_xor_sync(0xffffffffu, m0, 1));
        m0 = fmaxf(m0, __shfl_xor_sync(0xffffffffu, m0, 2));
        m1 = fmaxf(m1, __shfl_xor_sync(0xffffffffu, m1, 1));
        m1 = fmaxf(m1, __shfl_xor_sync(0xffffffffu, m1, 2));
        float s0 = 0.0f, s1 = 0.0f;
#pragma unroll
        for (int t = 0; t < 8; t++) {
            L[t][0] = __expf(L[t][0] - m0); s0 += L[t][0];
            L[t][1] = __expf(L[t][1] - m0); s0 += L[t][1];
            L[t][2] = __expf(L[t][2] - m1); s1 += L[t][2];
            L[t][3] = __expf(L[t][3] - m1); s1 += L[t][3];
        }
        s0 += __shfl_xor_sync(0xffffffffu, s0, 1);
        s0 += __shfl_xor_sync(0xffffffffu, s0, 2);
        s1 += __shfl_xor_sync(0xffffffffu, s1, 1);
        s1 += __shfl_xor_sync(0xffffffffu, s1, 2);
        float inv0 = 1.0f / s0, inv1 = 1.0f / s1;

        // PV with in-register P split
        float O[4][4];
#pragma unroll
        for (int t = 0; t < 4; t++)
#pragma unroll
            for (int v = 0; v < 4; v++) O[t][v] = 0.0f;
#pragma unroll
        for (int kc_ = 0; kc_ < 4; kc_++) {
            uint32_t ahi[4], alo[4];
            pack_split(L[2*kc_][0]*inv0,   L[2*kc_][1]*inv0,   ahi[0], alo[0]);
            pack_split(L[2*kc_][2]*inv1,   L[2*kc_][3]*inv1,   ahi[1], alo[1]);
            pack_split(L[2*kc_+1][0]*inv0, L[2*kc_+1][1]*inv0, ahi[2], alo[2]);
            pack_split(L[2*kc_+1][2]*inv1, L[2*kc_+1][3]*inv1, ahi[3], alo[3]);
#pragma unroll
            for (int g2 = 0; g2 < 2; g2++) {
                uint32_t bh[4], bl[4];
                uint32_t ad = (uint32_t)((g2 * 16 + brow) * 72 + kc_ * 16 + bkw) * 2;
                ldsm_x4(bh, sb + bo + VHI + ad);
                ldsm_x4(bl, sb + bo + VLO + ad);
                mma_bf16(O[2*g2],   ahi, bh[0], bh[1]);
                mma_bf16(O[2*g2],   ahi, bl[0], bl[1]);
                mma_bf16(O[2*g2],   alo, bh[0], bh[1]);
                mma_bf16(O[2*g2+1], ahi, bh[2], bh[3]);
                mma_bf16(O[2*g2+1], ahi, bl[2], bl[3]);
                mma_bf16(O[2*g2+1], alo, bh[2], bh[3]);
            }
        }

#pragma unroll
        for (int nt = 0; nt < 4; nt++) {
            size_t col = (size_t)h * DD + nt * 8 + c * 2;
            uint32_t h0, l0, h1, l1;
            pack_split(O[nt][0], O[nt][1], h0, l0);
            pack_split(O[nt][2], O[nt][3], h1, l1);
            *(uint32_t*)&g_xhi[trow0 * CC + col] = h0;
            *(uint32_t*)&g_xlo[trow0 * CC + col] = l0;
            *(uint32_t*)&g_xhi[trow1 * CC + col] = h1;
            *(uint32_t*)&g_xlo[trow1 * CC + col] = l1;
        }
    }
}

// ---------------- launcher (order chosen so ncu -s 5 captures gemm_q) ----------------
extern "C" void kernel_launch(void* const* d_in, const int* in_sizes, int n_in,
                              void* d_out, int out_size) {
    const float* X     = (const float*)d_in[0];
    const float* Ag    = (const float*)d_in[1];
    const float* wqkv  = (const float*)d_in[2];
    const float* wproj = (const float*)d_in[3];
    const float* bproj = (const float*)d_in[4];
    const float* cb    = (const float*)d_in[5];
    float* out = (float*)d_out;

    __nv_bfloat16 *pXhi, *pXlo, *pqhi, *pqlo, *pxhi, *pxlo, *pWqh, *pWql, *pWph, *pWpl;
    cudaGetSymbolAddress((void**)&pXhi, g_Xhi);
    cudaGetSymbolAddress((void**)&pXlo, g_Xlo);
    cudaGetSymbolAddress((void**)&pqhi, g_qhi);
    cudaGetSymbolAddress((void**)&pqlo, g_qlo);
    cudaGetSymbolAddress((void**)&pxhi, g_xhi);
    cudaGetSymbolAddress((void**)&pxlo, g_xlo);
    cudaGetSymbolAddress((void**)&pWqh, g_Wqt_hi);
    cudaGetSymbolAddress((void**)&pWql, g_Wqt_lo);
    cudaGetSymbolAddress((void**)&pWph, g_Wpt_hi);
    cudaGetSymbolAddress((void**)&pWpl, g_Wpt_lo);

    cudaFuncSetAttribute(gemm_bf16x3_mma,
                         cudaFuncAttributeMaxDynamicSharedMemorySize, GEMM_SMEM_BYTES);
    cudaFuncSetAttribute(pool_tc_kernel,
                         cudaFuncAttributeMaxDynamicSharedMemorySize, POOL_SMEM);
    cudaFuncSetAttribute(attn_tc_kernel,
                         cudaFuncAttributeMaxDynamicSharedMemorySize, ATT_SMEM_BYTES);

    // launches 1..5
    zero_kernel<<<(BB*KK*CC + 255) / 256, 256>>>();
    convertX_kernel<<<(BNTOT*CC) / (256*8), 256>>>(X);
    prepW_kernel<<<CC, 256>>>(wqkv, wproj);
    convertA_kernel<<<(BNTOT*KK) / (256*8), 256>>>(Ag);
    denom_kernel<<<BB * 16, 256>>>(Ag);
    // launch 6: captured by ncu (-s 5 -c 1) -> Q gemm
    {
        dim3 grid(BNTOT / 128, CC / 128);
        gemm_bf16x3_mma<<<grid, 256, GEMM_SMEM_BYTES>>>(pXhi, pXlo, pWqh, pWql,
                                                        nullptr, nullptr, pqhi, pqlo);
    }
    bias_kernel<<<BNTOT / 256, 256>>>(Ag, cb);
    pool_tc_kernel<<<BB * 32, 256, POOL_SMEM>>>();
    kcvc_kernel<<<BB * KK, 256>>>(wqkv);
    attn_tc_kernel<<<BNTOT / 128, 256, ATT_SMEM_BYTES>>>();
    {
        dim3 grid(BNTOT / 128, CC / 128);
        gemm_bf16x3_mma<<<grid, 256, GEMM_SMEM_BYTES>>>(pxhi, pxlo, pWph, pWpl,
                                                        bproj, out, nullptr, nullptr);
    }
}

// round 9
// speedup vs baseline: 1.3943x; 1.3943x over previous
#include <cuda_runtime.h>
#include <cuda_bf16.h>
#include <cuda_fp16.h>
#include <cstdint>
#include <math.h>

#define BB 4
#define NN 16384
#define CC 256
#define HH 8
#define KK 64
#define DD 32
#define BNTOT (BB*NN)

// ---------------- scratch ----------------
__device__ float g_S[BB*KK*CC];
__device__ float g_denom[BB*KK];
__device__ float g_bias[BNTOT*KK];
__device__ __half g_Xh[BNTOT*CC], g_Xl[BNTOT*CC];            // fp16 2-split of X
__device__ __half g_Ah[BNTOT*KK];                            // fp16 of A
__device__ __half g_xh[BNTOT*CC];                            // fp16 attn output
__device__ __half g_Wqt_hi[CC*CC], g_Wqt_lo[CC*CC];          // fp16 Wq^T hi/lo
__device__ __half g_Wpt_hi[CC*CC], g_Wpt_lo[CC*CC];          // fp16 Wproj^T hi/lo
__device__ __nv_bfloat16 g_qhi[BNTOT*CC], g_qlo[BNTOT*CC];   // bf16 split Q (attn input)
__device__ __nv_bfloat16 g_kchi[BB*HH*KK*DD], g_kclo[BB*HH*KK*DD];
__device__ __nv_bfloat16 g_vcThi[BB*HH*DD*KK], g_vcTlo[BB*HH*DD*KK];

// ---------------- helpers ----------------
__device__ __forceinline__ uint32_t smem_u32(const void* p) {
    uint32_t a;
    asm("{ .reg .u64 t; cvta.to.shared.u64 t, %1; cvt.u32.u64 %0, t; }" : "=r"(a) : "l"(p));
    return a;
}
#define CP16(dst, src) \
    asm volatile("cp.async.cg.shared.global [%0], [%1], 16;" :: "r"(dst), "l"(src))
#define CPCOMMIT() asm volatile("cp.async.commit_group;" ::: "memory")
#define CPWAIT(n)  asm volatile("cp.async.wait_group %0;" :: "n"(n) : "memory")

__device__ __forceinline__ void ldsm_x4(uint32_t* r, uint32_t addr) {
    asm volatile("ldmatrix.sync.aligned.m8n8.x4.shared.b16 {%0,%1,%2,%3}, [%4];"
                 : "=r"(r[0]), "=r"(r[1]), "=r"(r[2]), "=r"(r[3]) : "r"(addr));
}
__device__ __forceinline__ void ldsm_x4_t(uint32_t* r, uint32_t addr) {
    asm volatile("ldmatrix.sync.aligned.m8n8.x4.trans.shared.b16 {%0,%1,%2,%3}, [%4];"
                 : "=r"(r[0]), "=r"(r[1]), "=r"(r[2]), "=r"(r[3]) : "r"(addr));
}
__device__ __forceinline__ void mma_bf16(float* d, const uint32_t* a,
                                         uint32_t b0, uint32_t b1) {
    asm volatile(
        "mma.sync.aligned.m16n8k16.row.col.f32.bf16.bf16.f32 "
        "{%0,%1,%2,%3}, {%4,%5,%6,%7}, {%8,%9}, {%0,%1,%2,%3};"
        : "+f"(d[0]), "+f"(d[1]), "+f"(d[2]), "+f"(d[3])
        : "r"(a[0]), "r"(a[1]), "r"(a[2]), "r"(a[3]), "r"(b0), "r"(b1));
}
__device__ __forceinline__ void mma_fp16(float* d, const uint32_t* a,
                                         uint32_t b0, uint32_t b1) {
    asm volatile(
        "mma.sync.aligned.m16n8k16.row.col.f32.f16.f16.f32 "
        "{%0,%1,%2,%3}, {%4,%5,%6,%7}, {%8,%9}, {%0,%1,%2,%3};"
        : "+f"(d[0]), "+f"(d[1]), "+f"(d[2]), "+f"(d[3])
        : "r"(a[0]), "r"(a[1]), "r"(a[2]), "r"(a[3]), "r"(b0), "r"(b1));
}
__device__ __forceinline__ void pack_split(float a, float b, uint32_t& hi, uint32_t& lo) {
    __nv_bfloat16 ah = __float2bfloat16(a), bh = __float2bfloat16(b);
    __nv_bfloat16 al = __float2bfloat16(a - __bfloat162float(ah));
    __nv_bfloat16 bl = __float2bfloat16(b - __bfloat162float(bh));
    __nv_bfloat162 hp; hp.x = ah; hp.y = bh;
    __nv_bfloat162 lp; lp.x = al; lp.y = bl;
    hi = *(uint32_t*)&hp; lo = *(uint32_t*)&lp;
}

// ---------------- zero accumulators ----------------
__global__ void zero_kernel() {
    int i = blockIdx.x * blockDim.x + threadIdx.x;
    if (i < BB*KK*CC) g_S[i] = 0.0f;
    if (i < BB*KK)    g_denom[i] = 0.0f;
}

// ---------------- fp16 splits ----------------
__global__ __launch_bounds__(256) void convertX_kernel(const float* __restrict__ X) {
    size_t i = ((size_t)blockIdx.x * 256 + threadIdx.x) * 8;
    float4 a = *(const float4*)(X + i);
    float4 b = *(const float4*)(X + i + 4);
    float v[8] = {a.x, a.y, a.z, a.w, b.x, b.y, b.z, b.w};
    __half h[8], l[8];
#pragma unroll
    for (int j = 0; j < 8; j++) {
        h[j] = __float2half_rn(v[j]);
        l[j] = __float2half_rn(v[j] - __half2float(h[j]));
    }
    *(uint4*)&g_Xh[i] = *(const uint4*)h;
    *(uint4*)&g_Xl[i] = *(const uint4*)l;
}
__global__ __launch_bounds__(256) void convertA_kernel(const float* __restrict__ Ag) {
    size_t i = ((size_t)blockIdx.x * 256 + threadIdx.x) * 8;
    float4 a = *(const float4*)(Ag + i);
    float4 b = *(const float4*)(Ag + i + 4);
    float v[8] = {a.x, a.y, a.z, a.w, b.x, b.y, b.z, b.w};
    __half h[8];
#pragma unroll
    for (int j = 0; j < 8; j++) h[j] = __float2half_rn(v[j]);
    *(uint4*)&g_Ah[i] = *(const uint4*)h;
}

// ---------------- transposed fp16 hi/lo weights ----------------
__global__ __launch_bounds__(256) void prepW_kernel(const float* __restrict__ wqkv,
                                                    const float* __restrict__ wproj) {
    int n = blockIdx.x, k = threadIdx.x;
    float wq = wqkv[k * (3*CC) + n];
    float wp = wproj[k * CC + n];
    __half qh = __float2half_rn(wq);
    __half ph = __float2half_rn(wp);
    int o = n * CC + k;
    g_Wqt_hi[o] = qh;
    g_Wqt_lo[o] = __float2half_rn(wq - __half2float(qh));
    g_Wpt_hi[o] = ph;
    g_Wpt_lo[o] = __float2half_rn(wp - __half2float(ph));
}

// ---------------- exact fp32 denom ----------------
__global__ __launch_bounds__(256) void denom_kernel(const float* __restrict__ Ag) {
    __shared__ float red[4][64];
    int blk = blockIdx.x;
    int b = blk >> 4, seg = blk & 15;
    int k = threadIdx.x & 63, rr = threadIdx.x >> 6;
    float s = 0.0f;
    size_t base = (size_t)b * NN + seg * 1024;
#pragma unroll 4
    for (int i = 0; i < 256; i++) s += Ag[(base + rr + i * 4) * KK + k];
    red[rr][k] = s;
    __syncthreads();
    if (threadIdx.x < 64)
        atomicAdd(&g_denom[b * KK + threadIdx.x],
                  red[0][threadIdx.x] + red[1][threadIdx.x] +
                  red[2][threadIdx.x] + red[3][threadIdx.x]);
}

// ---------------- bias = A @ cluster_bias ----------------
__global__ __launch_bounds__(256) void bias_kernel(const float* __restrict__ Ag,
                                                   const float* __restrict__ cb) {
    __shared__ float cb_s[KK*KK];
    int tid = threadIdx.x;
    {
        const float4* cb4 = (const float4*)cb;
        float4* cbs4 = (float4*)cb_s;
        for (int i = tid; i < KK*KK/4; i += 256) cbs4[i] = cb4[i];
    }
    __syncthreads();
    size_t n = (size_t)blockIdx.x * 256 + tid;
    float biasr[64];
#pragma unroll
    for (int l = 0; l < 64; l++) biasr[l] = 0.0f;
    const float4* arow = (const float4*)(Ag + n * KK);
#pragma unroll
    for (int k4 = 0; k4 < 16; k4++) {
        float4 a4 = arow[k4];
        float avv[4] = {a4.x, a4.y, a4.z, a4.w};
#pragma unroll
        for (int kk = 0; kk < 4; kk++) {
            const float4* cbr = (const float4*)(cb_s + (k4 * 4 + kk) * 64);
#pragma unroll
            for (int l4 = 0; l4 < 16; l4++) {
                float4 c4 = cbr[l4];
                biasr[l4*4+0] += avv[kk] * c4.x;
                biasr[l4*4+1] += avv[kk] * c4.y;
                biasr[l4*4+2] += avv[kk] * c4.z;
                biasr[l4*4+3] += avv[kk] * c4.w;
            }
        }
    }
    float4* dst = (float4*)(g_bias + n * KK);
#pragma unroll
    for (int l4 = 0; l4 < 16; l4++)
        dst[l4] = make_float4(biasr[l4*4], biasr[l4*4+1], biasr[l4*4+2], biasr[l4*4+3]);
}

// ---------------- tensor-core pooling: S += A^T X (fp16 2-term, split-K atomics) --------
#define PX_ST 264
#define PA_ST 72
#define PX_SIZE (64*PX_ST)
#define PA_SIZE (64*PA_ST)
#define POOL_SMEM ((3*PX_SIZE + 3*PA_SIZE)*2)
__global__ __launch_bounds__(256, 1) void pool_tc_kernel() {
    extern __shared__ __half ps[];
    uint32_t sb = smem_u32(ps);
    int tid = threadIdx.x, lane = tid & 31, w = tid >> 5;
    int wm = w >> 2, wn = w & 3;
    int b = blockIdx.x >> 5;
    int nbase = (blockIdx.x & 31) * 512;
    const __half* Asrc[2] = {g_Ah, g_Ah};
    const __half* Xsrc[2] = {g_Xh, g_Xl};

    float acc[2][8][4];
#pragma unroll
    for (int i = 0; i < 2; i++)
#pragma unroll
        for (int j = 0; j < 8; j++)
#pragma unroll
            for (int r = 0; r < 4; r++) acc[i][j][r] = 0.0f;

    auto issue = [&](int c) {
        int s = c >> 3, kc_ = c & 7, buf = c % 3;
        size_t grow0 = (size_t)b * NN + nbase + kc_ * 64;
#pragma unroll
        for (int i = 0; i < 8; i++) {
            int idx = tid + i * 256;
            int row = idx >> 5, ch = idx & 31;
            CP16(sb + (uint32_t)(buf * PX_SIZE + row * PX_ST + ch * 8) * 2,
                 Xsrc[s] + (grow0 + row) * CC + ch * 8);
        }
#pragma unroll
        for (int i = 0; i < 2; i++) {
            int idx = tid + i * 256;
            int row = idx >> 3, ch = idx & 7;
            CP16(sb + (uint32_t)(3 * PX_SIZE + buf * PA_SIZE + row * PA_ST + ch * 8) * 2,
                 Asrc[s] + (grow0 + row) * KK + ch * 8);
        }
        CPCOMMIT();
    };

    issue(0); issue(1);
#pragma unroll 1
    for (int c = 0; c < 16; c++) {
        if (c < 14) { CPWAIT(1); } else { CPWAIT(0); }
        __syncthreads();
        if (c + 2 < 16) issue(c + 2);
        int buf = c % 3;
        uint32_t xb = sb + (uint32_t)(buf * PX_SIZE) * 2;
        uint32_t ab = sb + (uint32_t)(3 * PX_SIZE + buf * PA_SIZE) * 2;
#pragma unroll
        for (int kt = 0; kt < 4; kt++) {
            uint32_t af[2][4];
#pragma unroll
            for (int mt = 0; mt < 2; mt++) {
                uint32_t r[4];
                ldsm_x4_t(r, ab + (uint32_t)((kt * 16 + (lane & 15)) * PA_ST +
                                             wm * 32 + mt * 16 + (lane >> 4) * 8) * 2);
                af[mt][0] = r[0]; af[mt][1] = r[2]; af[mt][2] = r[1]; af[mt][3] = r[3];
            }
#pragma unroll
            for (int nb = 0; nb < 4; nb++) {
                uint32_t bfr[4];
                ldsm_x4_t(bfr, xb + (uint32_t)((kt * 16 + (lane & 15)) * PX_ST +
                                               wn * 64 + nb * 16 + (lane >> 4) * 8) * 2);
#pragma unroll
                for (int mt = 0; mt < 2; mt++) {
                    mma_fp16(acc[mt][nb*2],   af[mt], bfr[0], bfr[1]);
                    mma_fp16(acc[mt][nb*2+1], af[mt], bfr[2], bfr[3]);
                }
            }
        }
    }
#pragma unroll
    for (int mt = 0; mt < 2; mt++)
#pragma unroll
        for (int nt = 0; nt < 8; nt++) {
            int cl = wm * 32 + mt * 16 + (lane >> 2);
            int col = wn * 64 + nt * 8 + 2 * (lane & 3);
            float* d0 = &g_S[(b * KK + cl) * CC + col];
            atomicAdd(d0,     acc[mt][nt][0]);
            atomicAdd(d0 + 1, acc[mt][nt][1]);
            float* d1 = &g_S[(b * KK + cl + 8) * CC + col];
            atomicAdd(d1,     acc[mt][nt][2]);
            atomicAdd(d1 + 1, acc[mt][nt][3]);
        }
}

// ---------------- kc/vc from S -> scaled bf16 splits + transposed vc ----------------
__global__ __launch_bounds__(256) void kcvc_kernel(const float* __restrict__ wqkv) {
    int bk = blockIdx.x;
    int b = bk >> 6;
    int k = bk & 63;
    int t = threadIdx.x;
    __shared__ float s_row[CC];
    s_row[t] = g_S[bk * CC + t];
    __syncthreads();
    float inv = 1.0f / (g_denom[bk] + 1e-8f);
    float ak = 0.0f, av = 0.0f;
#pragma unroll 8
    for (int c = 0; c < CC; c++) {
        float s = s_row[c];
        ak += s * wqkv[c * (3*CC) + CC  + t];
        av += s * wqkv[c * (3*CC) + 2*CC + t];
    }
    int h = t >> 5, dd = t & 31;
    const float SC = 0.17677669529663689f;
    float kcv = ak * inv * SC;
    float vcv = av * inv;
    size_t ok = ((size_t)(b * HH + h) * KK + k) * DD + dd;
    size_t ov = ((size_t)(b * HH + h) * DD + dd) * KK + k;
    __nv_bfloat16 kh = __float2bfloat16(kcv);
    __nv_bfloat16 vh = __float2bfloat16(vcv);
    g_kchi[ok] = kh;  g_kclo[ok] = __float2bfloat16(kcv - __bfloat162float(kh));
    g_vcThi[ov] = vh; g_vcTlo[ov] = __float2bfloat16(vcv - __bfloat162float(vh));
}

// ---------------- HMMA fp16 2-term GEMM: C = A @ W^T, ext-K 512 (16 chunks of 32) ------
#define AST 40
#define STAGE_ELE (128 * AST)
#define GEMM_SMEM_BYTES (2 * 3 * STAGE_ELE * 2)   // 61440 B
__global__ __launch_bounds__(256, 2) void gemm_fp16x2_mma(
    const __half* __restrict__ Am,
    const __half* __restrict__ Whi, const __half* __restrict__ Wlo,
    const float* __restrict__ bias, float* __restrict__ Cout,
    __nv_bfloat16* __restrict__ Ohi, __nv_bfloat16* __restrict__ Olo) {
    extern __shared__ __half smemh[];
    __half* As = smemh;
    __half* Bs = smemh + 3 * STAGE_ELE;
    uint32_t a_sm = smem_u32(As);
    uint32_t b_sm = smem_u32(Bs);

    int tid = threadIdx.x;
    int lane = tid & 31, w = tid >> 5;
    int wr = w >> 2, wc = w & 3;
    size_t mbase = (size_t)blockIdx.x * 128;
    int nbase = blockIdx.y * 128;

    const __half* Wsp[2] = {Whi, Wlo};

    int ldrow = tid >> 2;
    int ldwd  = tid & 3;

    float acc[4][4][4];
#pragma unroll
    for (int i = 0; i < 4; i++)
#pragma unroll
        for (int j = 0; j < 4; j++)
#pragma unroll
            for (int r = 0; r < 4; r++) acc[i][j][r] = 0.0f;

    auto issue = [&](int c) {
        int s = c >> 3;                  // product 0..1
        int ko = (c & 7) * 32;
        const __half* Wp = Wsp[s];
        uint32_t sa = a_sm + (uint32_t)((c % 3) * STAGE_ELE) * 2;
        uint32_t sb = b_sm + (uint32_t)((c % 3) * STAGE_ELE) * 2;
#pragma unroll
        for (int t = 0; t < 2; t++) {
            int row = ldrow + t * 64;
            CP16(sa + (uint32_t)(row * AST + ldwd * 8) * 2,
                 Am + (mbase + row) * CC + ko + ldwd * 8);
            CP16(sb + (uint32_t)(row * AST + ldwd * 8) * 2,
                 Wp + (size_t)(nbase + row) * CC + ko + ldwd * 8);
        }
        CPCOMMIT();
    };

    int arow = (lane & 7) + 8 * ((lane >> 3) & 1);
    int akw  = (lane >> 4) * 8;
    int brow = (lane & 7) + 8 * ((lane >> 4) & 1);
    int bkw  = ((lane >> 3) & 1) * 8;

    auto compute = [&](int stage) {
        uint32_t sa = a_sm + (uint32_t)(stage * STAGE_ELE) * 2;
        uint32_t sb = b_sm + (uint32_t)(stage * STAGE_ELE) * 2;
#pragma unroll
        for (int ks = 0; ks < 32; ks += 16) {
            uint32_t afr[4][4];
#pragma unroll
            for (int mt = 0; mt < 4; mt++)
                ldsm_x4(afr[mt], sa + (uint32_t)(((wr * 64 + mt * 16 + arow) * AST) + ks + akw) * 2);
            uint32_t bfr[2][4];
#pragma unroll
            for (int nt2 = 0; nt2 < 2; nt2++)
                ldsm_x4(bfr[nt2], sb + (uint32_t)(((wc * 32 + nt2 * 16 + brow) * AST) + ks + bkw) * 2);
#pragma unroll
            for (int mt = 0; mt < 4; mt++)
#pragma unroll
                for (int nt = 0; nt < 4; nt++)
                    mma_fp16(acc[mt][nt], afr[mt],
                             bfr[nt >> 1][(nt & 1) * 2],
                             bfr[nt >> 1][(nt & 1) * 2 + 1]);
        }
    };

    issue(0);
    issue(1);
#pragma unroll 1
    for (int c = 0; c < 16; c++) {
        if (c < 14) { CPWAIT(1); } else { CPWAIT(0); }
        __syncthreads();
        if (c + 2 < 16) issue(c + 2);
        compute(c % 3);
    }

    int g = lane >> 2, ti = lane & 3;
#pragma unroll
    for (int mt = 0; mt < 4; mt++) {
#pragma unroll
        for (int nt = 0; nt < 4; nt++) {
            size_t row = mbase + wr * 64 + mt * 16 + g;
            int col = nbase + wc * 32 + nt * 8 + ti * 2;
            if (Cout) {
                float bx = 0.0f, by = 0.0f;
                if (bias) { bx = bias[col]; by = bias[col + 1]; }
                float2 v0, v1;
                v0.x = acc[mt][nt][0] + bx; v0.y = acc[mt][nt][1] + by;
                v1.x = acc[mt][nt][2] + bx; v1.y = acc[mt][nt][3] + by;
                *(float2*)&Cout[row * CC + col] = v0;
                *(float2*)&Cout[(row + 8) * CC + col] = v1;
            } else {
                uint32_t h0, l0, h1, l1;
                pack_split(acc[mt][nt][0], acc[mt][nt][1], h0, l0);
                pack_split(acc[mt][nt][2], acc[mt][nt][3], h1, l1);
                *(uint32_t*)&Ohi[row * CC + col] = h0;
                *(uint32_t*)&Olo[row * CC + col] = l0;
                *(uint32_t*)&Ohi[(row + 8) * CC + col] = h1;
                *(uint32_t*)&Olo[(row + 8) * CC + col] = l1;
            }
        }
    }
}

// ---------------- tensor-core attention (Round-7 config; fp16 x output) ----------------
#define ATT_BUF_BYTES 19456
#define ATT_SMEM_BYTES (2 * ATT_BUF_BYTES)
__global__ __launch_bounds__(256) void attn_tc_kernel() {
    extern __shared__ __nv_bfloat16 smn[];
    uint32_t sb = smem_u32(smn);
    int tid = threadIdx.x, lane = tid & 31, w = tid >> 5;
    size_t tok0 = (size_t)blockIdx.x * 128;
    int b = blockIdx.x >> 7;
    int r = lane >> 2, c = lane & 3;
    size_t trow0 = tok0 + (size_t)w * 16 + r;
    size_t trow1 = trow0 + 8;

    const uint32_t KHI = 0, KLO = 5120, VHI = 10240, VLO = 14848;

    auto issue_head = [&](int h) {
        uint32_t bo = (uint32_t)(h & 1) * ATT_BUF_BYTES;
        {
            int rr = tid >> 2, cc = tid & 3;
            size_t src = ((size_t)(b * HH + h) * KK + rr) * DD + cc * 8;
            uint32_t d = (uint32_t)(rr * 40 + cc * 8) * 2;
            CP16(sb + bo + KHI + d, g_kchi + src);
            CP16(sb + bo + KLO + d, g_kclo + src);
        }
        {
            int rr = tid >> 3, cc = tid & 7;
            size_t src = ((size_t)(b * HH + h) * DD + rr) * KK + cc * 8;
            uint32_t d = (uint32_t)(rr * 72 + cc * 8) * 2;
            CP16(sb + bo + VHI + d, g_vcThi + src);
            CP16(sb + bo + VLO + d, g_vcTlo + src);
        }
        CPCOMMIT();
    };
    issue_head(0);

    // bias fragments, loaded once
    float Lbias[8][4];
#pragma unroll
    for (int t = 0; t < 8; t++) {
        float2 b0 = *(const float2*)(g_bias + trow0 * KK + t * 8 + c * 2);
        float2 b1 = *(const float2*)(g_bias + trow1 * KK + t * 8 + c * 2);
        Lbias[t][0] = b0.x; Lbias[t][1] = b0.y;
        Lbias[t][2] = b1.x; Lbias[t][3] = b1.y;
    }

    int brow = (lane & 7) + 8 * ((lane >> 4) & 1);
    int bkw  = ((lane >> 3) & 1) * 8;

#pragma unroll 1
    for (int h = 0; h < HH; h++) {
        CPWAIT(0);
        __syncthreads();
        if (h + 1 < HH) issue_head(h + 1);
        uint32_t bo = (uint32_t)(h & 1) * ATT_BUF_BYTES;

        uint32_t qhi[2][4], qlo[2][4];
#pragma unroll
        for (int ks = 0; ks < 2; ks++) {
            size_t col = (size_t)h * DD + ks * 16 + c * 2;
            qhi[ks][0] = *(const uint32_t*)(g_qhi + trow0 * CC + col);
            qhi[ks][1] = *(const uint32_t*)(g_qhi + trow1 * CC + col);
            qhi[ks][2] = *(const uint32_t*)(g_qhi + trow0 * CC + col + 8);
            qhi[ks][3] = *(const uint32_t*)(g_qhi + trow1 * CC + col + 8);
            qlo[ks][0] = *(const uint32_t*)(g_qlo + trow0 * CC + col);
            qlo[ks][1] = *(const uint32_t*)(g_qlo + trow1 * CC + col);
            qlo[ks][2] = *(const uint32_t*)(g_qlo + trow0 * CC + col + 8);
            qlo[ks][3] = *(const uint32_t*)(g_qlo + trow1 * CC + col + 8);
        }

        float L[8][4];
#pragma unroll
        for (int t = 0; t < 8; t++)
#pragma unroll
            for (int v = 0; v < 4; v++) L[t][v] = Lbias[t][v];
#pragma unroll
        for (int g2 = 0; g2 < 4; g2++) {
#pragma unroll
            for (int ks = 0; ks < 2; ks++) {
                uint32_t bh[4], bl[4];
                uint32_t ad = (uint32_t)((g2 * 16 + brow) * 40 + ks * 16 + bkw) * 2;
                ldsm_x4(bh, sb + bo + KHI + ad);
                ldsm_x4(bl, sb + bo + KLO + ad);
                mma_bf16(L[2*g2],   qhi[ks], bh[0], bh[1]);
                mma_bf16(L[2*g2],   qhi[ks], bl[0], bl[1]);
                mma_bf16(L[2*g2],   qlo[ks], bh[0], bh[1]);
                mma_bf16(L[2*g2+1], qhi[ks], bh[2], bh[3]);
                mma_bf16(L[2*g2+1], qhi[ks], bl[2], bl[3]);
                mma_bf16(L[2*g2+1], qlo[ks], bh[2], bh[3]);
            }
        }

        float m0 = -1e30f, m1 = -1e30f;
#pragma unroll
        for (int t = 0; t < 8; t++) {
            m0 = fmaxf(m0, fmaxf(L[t][0], L[t][1]));
            m1 = fmaxf(m1, fmaxf(L[t][2], L[t][3]));
        }
        m0 = fmaxf(m0, __shfl_xor_sync(0xffffffffu, m0, 1));
        m0 = fmaxf(m0, __shfl_xor_sync(0xffffffffu, m0, 2));
        m1 = fmaxf(m1, __shfl_xor_sync(0xffffffffu, m1, 1));
        m1 = fmaxf(m1, __shfl_xor_sync(0xffffffffu, m1, 2));
        float s0 = 0.0f, s1 = 0.0f;
#pragma unroll
        for (int t = 0; t < 8; t++) {
            L[t][0] = __expf(L[t][0] - m0); s0 += L[t][0];
            L[t][1] = __expf(L[t][1] - m0); s0 += L[t][1];
            L[t][2] = __expf(L[t][2] - m1); s1 += L[t][2];
            L[t][3] = __expf(L[t][3] - m1); s1 += L[t][3];
        }
        s0 += __shfl_xor_sync(0xffffffffu, s0, 1);
        s0 += __shfl_xor_sync(0xffffffffu, s0, 2);
        s1 += __shfl_xor_sync(0xffffffffu, s1, 1);
        s1 += __shfl_xor_sync(0xffffffffu, s1, 2);
        float inv0 = 1.0f / s0, inv1 = 1.0f / s1;

        float O[4][4];
#pragma unroll
        for (int t = 0; t < 4; t++)
#pragma unroll
            for (int v = 0; v < 4; v++) O[t][v] = 0.0f;
#pragma unroll
        for (int kc_ = 0; kc_ < 4; kc_++) {
            uint32_t ahi[4], alo[4];
            pack_split(L[2*kc_][0]*inv0,   L[2*kc_][1]*inv0,   ahi[0], alo[0]);
            pack_split(L[2*kc_][2]*inv1,   L[2*kc_][3]*inv1,   ahi[1], alo[1]);
            pack_split(L[2*kc_+1][0]*inv0, L[2*kc_+1][1]*inv0, ahi[2], alo[2]);
            pack_split(L[2*kc_+1][2]*inv1, L[2*kc_+1][3]*inv1, ahi[3], alo[3]);
#pragma unroll
            for (int g2 = 0; g2 < 2; g2++) {
                uint32_t bh[4], bl[4];
                uint32_t ad = (uint32_t)((g2 * 16 + brow) * 72 + kc_ * 16 + bkw) * 2;
                ldsm_x4(bh, sb + bo + VHI + ad);
                ldsm_x4(bl, sb + bo + VLO + ad);
                mma_bf16(O[2*g2],   ahi, bh[0], bh[1]);
                mma_bf16(O[2*g2],   ahi, bl[0], bl[1]);
                mma_bf16(O[2*g2],   alo, bh[0], bh[1]);
                mma_bf16(O[2*g2+1], ahi, bh[2], bh[3]);
                mma_bf16(O[2*g2+1], ahi, bl[2], bl[3]);
                mma_bf16(O[2*g2+1], alo, bh[2], bh[3]);
            }
        }

        // store x as single fp16 (Wproj carries the 2-term split)
#pragma unroll
        for (int nt = 0; nt < 4; nt++) {
            size_t col = (size_t)h * DD + nt * 8 + c * 2;
            __half2 v0; v0.x = __float2half_rn(O[nt][0]); v0.y = __float2half_rn(O[nt][1]);
            __half2 v1; v1.x = __float2half_rn(O[nt][2]); v1.y = __float2half_rn(O[nt][3]);
            *(__half2*)&g_xh[trow0 * CC + col] = v0;
            *(__half2*)&g_xh[trow1 * CC + col] = v1;
        }
    }
}

// ---------------- launcher ----------------
extern "C" void kernel_launch(void* const* d_in, const int* in_sizes, int n_in,
                              void* d_out, int out_size) {
    const float* X     = (const float*)d_in[0];
    const float* Ag    = (const float*)d_in[1];
    const float* wqkv  = (const float*)d_in[2];
    const float* wproj = (const float*)d_in[3];
    const float* bproj = (const float*)d_in[4];
    const float* cb    = (const float*)d_in[5];
    float* out = (float*)d_out;

    __half *pXh, *pxh, *pWqh, *pWql, *pWph, *pWpl;
    __nv_bfloat16 *pqhi, *pqlo;
    cudaGetSymbolAddress((void**)&pXh, g_Xh);
    cudaGetSymbolAddress((void**)&pxh, g_xh);
    cudaGetSymbolAddress((void**)&pWqh, g_Wqt_hi);
    cudaGetSymbolAddress((void**)&pWql, g_Wqt_lo);
    cudaGetSymbolAddress((void**)&pWph, g_Wpt_hi);
    cudaGetSymbolAddress((void**)&pWpl, g_Wpt_lo);
    cudaGetSymbolAddress((void**)&pqhi, g_qhi);
    cudaGetSymbolAddress((void**)&pqlo, g_qlo);

    cudaFuncSetAttribute(gemm_fp16x2_mma,
                         cudaFuncAttributeMaxDynamicSharedMemorySize, GEMM_SMEM_BYTES);
    cudaFuncSetAttribute(pool_tc_kernel,
                         cudaFuncAttributeMaxDynamicSharedMemorySize, POOL_SMEM);
    cudaFuncSetAttribute(attn_tc_kernel,
                         cudaFuncAttributeMaxDynamicSharedMemorySize, ATT_SMEM_BYTES);

    zero_kernel<<<(BB*KK*CC + 255) / 256, 256>>>();
    convertX_kernel<<<(BNTOT*CC) / (256*8), 256>>>(X);
    prepW_kernel<<<CC, 256>>>(wqkv, wproj);
    convertA_kernel<<<(BNTOT*KK) / (256*8), 256>>>(Ag);
    denom_kernel<<<BB * 16, 256>>>(Ag);
    {   // Q = X @ Wq (fp16 2-term), bf16 split output for attn
        dim3 grid(BNTOT / 128, CC / 128);
        gemm_fp16x2_mma<<<grid, 256, GEMM_SMEM_BYTES>>>(pXh, pWqh, pWql,
                                                        nullptr, nullptr, pqhi, pqlo);
    }
    bias_kernel<<<BNTOT / 256, 256>>>(Ag, cb);
    pool_tc_kernel<<<BB * 32, 256, POOL_SMEM>>>();
    kcvc_kernel<<<BB * KK, 256>>>(wqkv);
    attn_tc_kernel<<<BNTOT / 128, 256, ATT_SMEM_BYTES>>>();
    {   // out = x @ Wproj + b (fp16 2-term)
        dim3 grid(BNTOT / 128, CC / 128);
        gemm_fp16x2_mma<<<grid, 256, GEMM_SMEM_BYTES>>>(pxh, pWph, pWpl,
                                                        bproj, out, nullptr, nullptr);
    }
}

// round 10
// speedup vs baseline: 1.4134x; 1.0137x over previous
#include <cuda_runtime.h>
#include <cuda_bf16.h>
#include <cuda_fp16.h>
#include <cstdint>
#include <math.h>

#define BB 4
#define NN 16384
#define CC 256
#define HH 8
#define KK 64
#define DD 32
#define BNTOT (BB*NN)

// ---------------- scratch ----------------
__device__ float g_S[BB*KK*CC];
__device__ float g_denom[BB*KK];
__device__ float g_bias[BNTOT*KK];
__device__ __half g_Xh[BNTOT*CC], g_Xl[BNTOT*CC];
__device__ __half g_Ah[BNTOT*KK];
__device__ __half g_xh[BNTOT*CC];
__device__ __half g_Wqt_hi[CC*CC], g_Wqt_lo[CC*CC];
__device__ __half g_Wpt_hi[CC*CC], g_Wpt_lo[CC*CC];
__device__ __nv_bfloat16 g_qhi[BNTOT*CC], g_qlo[BNTOT*CC];
__device__ __nv_bfloat16 g_kchi[BB*HH*KK*DD], g_kclo[BB*HH*KK*DD];
__device__ __nv_bfloat16 g_vcThi[BB*HH*DD*KK], g_vcTlo[BB*HH*DD*KK];

// ---------------- helpers ----------------
__device__ __forceinline__ uint32_t smem_u32(const void* p) {
    uint32_t a;
    asm("{ .reg .u64 t; cvta.to.shared.u64 t, %1; cvt.u32.u64 %0, t; }" : "=r"(a) : "l"(p));
    return a;
}
#define CP16(dst, src) \
    asm volatile("cp.async.cg.shared.global [%0], [%1], 16;" :: "r"(dst), "l"(src))
#define CPCOMMIT() asm volatile("cp.async.commit_group;" ::: "memory")
#define CPWAIT(n)  asm volatile("cp.async.wait_group %0;" :: "n"(n) : "memory")

__device__ __forceinline__ void ldsm_x4(uint32_t* r, uint32_t addr) {
    asm volatile("ldmatrix.sync.aligned.m8n8.x4.shared.b16 {%0,%1,%2,%3}, [%4];"
                 : "=r"(r[0]), "=r"(r[1]), "=r"(r[2]), "=r"(r[3]) : "r"(addr));
}
__device__ __forceinline__ void ldsm_x4_t(uint32_t* r, uint32_t addr) {
    asm volatile("ldmatrix.sync.aligned.m8n8.x4.trans.shared.b16 {%0,%1,%2,%3}, [%4];"
                 : "=r"(r[0]), "=r"(r[1]), "=r"(r[2]), "=r"(r[3]) : "r"(addr));
}
__device__ __forceinline__ void mma_bf16(float* d, const uint32_t* a,
                                         uint32_t b0, uint32_t b1) {
    asm volatile(
        "mma.sync.aligned.m16n8k16.row.col.f32.bf16.bf16.f32 "
        "{%0,%1,%2,%3}, {%4,%5,%6,%7}, {%8,%9}, {%0,%1,%2,%3};"
        : "+f"(d[0]), "+f"(d[1]), "+f"(d[2]), "+f"(d[3])
        : "r"(a[0]), "r"(a[1]), "r"(a[2]), "r"(a[3]), "r"(b0), "r"(b1));
}
__device__ __forceinline__ void mma_fp16(float* d, const uint32_t* a,
                                         uint32_t b0, uint32_t b1) {
    asm volatile(
        "mma.sync.aligned.m16n8k16.row.col.f32.f16.f16.f32 "
        "{%0,%1,%2,%3}, {%4,%5,%6,%7}, {%8,%9}, {%0,%1,%2,%3};"
        : "+f"(d[0]), "+f"(d[1]), "+f"(d[2]), "+f"(d[3])
        : "r"(a[0]), "r"(a[1]), "r"(a[2]), "r"(a[3]), "r"(b0), "r"(b1));
}
__device__ __forceinline__ void pack_split(float a, float b, uint32_t& hi, uint32_t& lo) {
    __nv_bfloat16 ah = __float2bfloat16(a), bh = __float2bfloat16(b);
    __nv_bfloat16 al = __float2bfloat16(a - __bfloat162float(ah));
    __nv_bfloat16 bl = __float2bfloat16(b - __bfloat162float(bh));
    __nv_bfloat162 hp; hp.x = ah; hp.y = bh;
    __nv_bfloat162 lp; lp.x = al; lp.y = bl;
    hi = *(uint32_t*)&hp; lo = *(uint32_t*)&lp;
}

// ---------------- zero accumulators ----------------
__global__ void zero_kernel() {
    int i = blockIdx.x * blockDim.x + threadIdx.x;
    if (i < BB*KK*CC) g_S[i] = 0.0f;
    if (i < BB*KK)    g_denom[i] = 0.0f;
}

// ---------------- fp16 splits ----------------
__global__ __launch_bounds__(256) void convertX_kernel(const float* __restrict__ X) {
    size_t i = ((size_t)blockIdx.x * 256 + threadIdx.x) * 8;
    float4 a = *(const float4*)(X + i);
    float4 b = *(const float4*)(X + i + 4);
    float v[8] = {a.x, a.y, a.z, a.w, b.x, b.y, b.z, b.w};
    __half h[8], l[8];
#pragma unroll
    for (int j = 0; j < 8; j++) {
        h[j] = __float2half_rn(v[j]);
        l[j] = __float2half_rn(v[j] - __half2float(h[j]));
    }
    *(uint4*)&g_Xh[i] = *(const uint4*)h;
    *(uint4*)&g_Xl[i] = *(const uint4*)l;
}

// convertA + fused denom (column sums of A)
__global__ __launch_bounds__(256) void convertA_kernel(const float* __restrict__ Ag) {
    __shared__ float dsum[KK];
    int tid = threadIdx.x, lane = tid & 31;
    if (tid < KK) dsum[tid] = 0.0f;
    __syncthreads();
    size_t i = ((size_t)blockIdx.x * 256 + tid) * 8;
    float4 a = *(const float4*)(Ag + i);
    float4 b = *(const float4*)(Ag + i + 4);
    float v[8] = {a.x, a.y, a.z, a.w, b.x, b.y, b.z, b.w};
    __half h[8];
#pragma unroll
    for (int j = 0; j < 8; j++) h[j] = __float2half_rn(v[j]);
    *(uint4*)&g_Ah[i] = *(const uint4*)h;
    // column reduction: lanes {l, l+8, l+16, l+24} share the same 8-col set
#pragma unroll
    for (int j = 0; j < 8; j++) {
        v[j] += __shfl_down_sync(0xffffffffu, v[j], 16);
        v[j] += __shfl_down_sync(0xffffffffu, v[j], 8);
    }
    if (lane < 8) {
        int k0 = (tid & 7) * 8;
#pragma unroll
        for (int j = 0; j < 8; j++) atomicAdd(&dsum[k0 + j], v[j]);
    }
    __syncthreads();
    int b_ = blockIdx.x >> 9;   // 512 blocks per batch (2048 elems/block, NN*KK=1M/batch)
    if (tid < KK) atomicAdd(&g_denom[b_ * KK + tid], dsum[tid]);
}

// ---------------- transposed fp16 hi/lo weights ----------------
__global__ __launch_bounds__(256) void prepW_kernel(const float* __restrict__ wqkv,
                                                    const float* __restrict__ wproj) {
    int n = blockIdx.x, k = threadIdx.x;
    float wq = wqkv[k * (3*CC) + n];
    float wp = wproj[k * CC + n];
    __half qh = __float2half_rn(wq);
    __half ph = __float2half_rn(wp);
    int o = n * CC + k;
    g_Wqt_hi[o] = qh;
    g_Wqt_lo[o] = __float2half_rn(wq - __half2float(qh));
    g_Wpt_hi[o] = ph;
    g_Wpt_lo[o] = __float2half_rn(wp - __half2float(ph));
}

// ---------------- bias = A @ cluster_bias ----------------
__global__ __launch_bounds__(256) void bias_kernel(const float* __restrict__ Ag,
                                                   const float* __restrict__ cb) {
    __shared__ float cb_s[KK*KK];
    int tid = threadIdx.x;
    {
        const float4* cb4 = (const float4*)cb;
        float4* cbs4 = (float4*)cb_s;
        for (int i = tid; i < KK*KK/4; i += 256) cbs4[i] = cb4[i];
    }
    __syncthreads();
    size_t n = (size_t)blockIdx.x * 256 + tid;
    float biasr[64];
#pragma unroll
    for (int l = 0; l < 64; l++) biasr[l] = 0.0f;
    const float4* arow = (const float4*)(Ag + n * KK);
#pragma unroll
    for (int k4 = 0; k4 < 16; k4++) {
        float4 a4 = arow[k4];
        float avv[4] = {a4.x, a4.y, a4.z, a4.w};
#pragma unroll
        for (int kk = 0; kk < 4; kk++) {
            const float4* cbr = (const float4*)(cb_s + (k4 * 4 + kk) * 64);
#pragma unroll
            for (int l4 = 0; l4 < 16; l4++) {
                float4 c4 = cbr[l4];
                biasr[l4*4+0] += avv[kk] * c4.x;
                biasr[l4*4+1] += avv[kk] * c4.y;
                biasr[l4*4+2] += avv[kk] * c4.z;
                biasr[l4*4+3] += avv[kk] * c4.w;
            }
        }
    }
    float4* dst = (float4*)(g_bias + n * KK);
#pragma unroll
    for (int l4 = 0; l4 < 16; l4++)
        dst[l4] = make_float4(biasr[l4*4], biasr[l4*4+1], biasr[l4*4+2], biasr[l4*4+3]);
}

// ---------------- tensor-core pooling: S += A^T X (fp16 2-term, split-K atomics) --------
#define PX_ST 264
#define PA_ST 72
#define PX_SIZE (64*PX_ST)
#define PA_SIZE (64*PA_ST)
#define POOL_SMEM ((3*PX_SIZE + 3*PA_SIZE)*2)
__global__ __launch_bounds__(256, 1) void pool_tc_kernel() {
    extern __shared__ __half ps[];
    uint32_t sb = smem_u32(ps);
    int tid = threadIdx.x, lane = tid & 31, w = tid >> 5;
    int wm = w >> 2, wn = w & 3;
    int b = blockIdx.x >> 5;
    int nbase = (blockIdx.x & 31) * 512;
    const __half* Asrc[2] = {g_Ah, g_Ah};
    const __half* Xsrc[2] = {g_Xh, g_Xl};

    float acc[2][8][4];
#pragma unroll
    for (int i = 0; i < 2; i++)
#pragma unroll
        for (int j = 0; j < 8; j++)
#pragma unroll
            for (int r = 0; r < 4; r++) acc[i][j][r] = 0.0f;

    auto issue = [&](int c) {
        int s = c >> 3, kc_ = c & 7, buf = c % 3;
        size_t grow0 = (size_t)b * NN + nbase + kc_ * 64;
#pragma unroll
        for (int i = 0; i < 8; i++) {
            int idx = tid + i * 256;
            int row = idx >> 5, ch = idx & 31;
            CP16(sb + (uint32_t)(buf * PX_SIZE + row * PX_ST + ch * 8) * 2,
                 Xsrc[s] + (grow0 + row) * CC + ch * 8);
        }
#pragma unroll
        for (int i = 0; i < 2; i++) {
            int idx = tid + i * 256;
            int row = idx >> 3, ch = idx & 7;
            CP16(sb + (uint32_t)(3 * PX_SIZE + buf * PA_SIZE + row * PA_ST + ch * 8) * 2,
                 Asrc[s] + (grow0 + row) * KK + ch * 8);
        }
        CPCOMMIT();
    };

    issue(0); issue(1);
#pragma unroll 1
    for (int c = 0; c < 16; c++) {
        if (c < 14) { CPWAIT(1); } else { CPWAIT(0); }
        __syncthreads();
        if (c + 2 < 16) issue(c + 2);
        int buf = c % 3;
        uint32_t xb = sb + (uint32_t)(buf * PX_SIZE) * 2;
        uint32_t ab = sb + (uint32_t)(3 * PX_SIZE + buf * PA_SIZE) * 2;
#pragma unroll
        for (int kt = 0; kt < 4; kt++) {
            uint32_t af[2][4];
#pragma unroll
            for (int mt = 0; mt < 2; mt++) {
                uint32_t r[4];
                ldsm_x4_t(r, ab + (uint32_t)((kt * 16 + (lane & 15)) * PA_ST +
                                             wm * 32 + mt * 16 + (lane >> 4) * 8) * 2);
                af[mt][0] = r[0]; af[mt][1] = r[2]; af[mt][2] = r[1]; af[mt][3] = r[3];
            }
#pragma unroll
            for (int nb = 0; nb < 4; nb++) {
                uint32_t bfr[4];
                ldsm_x4_t(bfr, xb + (uint32_t)((kt * 16 + (lane & 15)) * PX_ST +
                                               wn * 64 + nb * 16 + (lane >> 4) * 8) * 2);
#pragma unroll
                for (int mt = 0; mt < 2; mt++) {
                    mma_fp16(acc[mt][nb*2],   af[mt], bfr[0], bfr[1]);
                    mma_fp16(acc[mt][nb*2+1], af[mt], bfr[2], bfr[3]);
                }
            }
        }
    }
#pragma unroll
    for (int mt = 0; mt < 2; mt++)
#pragma unroll
        for (int nt = 0; nt < 8; nt++) {
            int cl = wm * 32 + mt * 16 + (lane >> 2);
            int col = wn * 64 + nt * 8 + 2 * (lane & 3);
            float* d0 = &g_S[(b * KK + cl) * CC + col];
            atomicAdd(d0,     acc[mt][nt][0]);
            atomicAdd(d0 + 1, acc[mt][nt][1]);
            float* d1 = &g_S[(b * KK + cl + 8) * CC + col];
            atomicAdd(d1,     acc[mt][nt][2]);
            atomicAdd(d1 + 1, acc[mt][nt][3]);
        }
}

// ---------------- kc/vc from S -> scaled bf16 splits + transposed vc ----------------
__global__ __launch_bounds__(256) void kcvc_kernel(const float* __restrict__ wqkv) {
    int bk = blockIdx.x;
    int b = bk >> 6;
    int k = bk & 63;
    int t = threadIdx.x;
    __shared__ float s_row[CC];
    s_row[t] = g_S[bk * CC + t];
    __syncthreads();
    float inv = 1.0f / (g_denom[bk] + 1e-8f);
    float ak = 0.0f, av = 0.0f;
#pragma unroll 8
    for (int c = 0; c < CC; c++) {
        float s = s_row[c];
        ak += s * wqkv[c * (3*CC) + CC  + t];
        av += s * wqkv[c * (3*CC) + 2*CC + t];
    }
    int h = t >> 5, dd = t & 31;
    const float SC = 0.17677669529663689f;
    float kcv = ak * inv * SC;
    float vcv = av * inv;
    size_t ok = ((size_t)(b * HH + h) * KK + k) * DD + dd;
    size_t ov = ((size_t)(b * HH + h) * DD + dd) * KK + k;
    __nv_bfloat16 kh = __float2bfloat16(kcv);
    __nv_bfloat16 vh = __float2bfloat16(vcv);
    g_kchi[ok] = kh;  g_kclo[ok] = __float2bfloat16(kcv - __bfloat162float(kh));
    g_vcThi[ov] = vh; g_vcTlo[ov] = __float2bfloat16(vcv - __bfloat162float(vh));
}

// ---------------- HMMA fp16 2-term GEMM (unchanged from R9) ----------------
#define AST 40
#define STAGE_ELE (128 * AST)
#define GEMM_SMEM_BYTES (2 * 3 * STAGE_ELE * 2)
__global__ __launch_bounds__(256, 2) void gemm_fp16x2_mma(
    const __half* __restrict__ Am,
    const __half* __restrict__ Whi, const __half* __restrict__ Wlo,
    const float* __restrict__ bias, float* __restrict__ Cout,
    __nv_bfloat16* __restrict__ Ohi, __nv_bfloat16* __restrict__ Olo) {
    extern __shared__ __half smemh[];
    __half* As = smemh;
    __half* Bs = smemh + 3 * STAGE_ELE;
    uint32_t a_sm = smem_u32(As);
    uint32_t b_sm = smem_u32(Bs);

    int tid = threadIdx.x;
    int lane = tid & 31, w = tid >> 5;
    int wr = w >> 2, wc = w & 3;
    size_t mbase = (size_t)blockIdx.x * 128;
    int nbase = blockIdx.y * 128;

    const __half* Wsp[2] = {Whi, Wlo};

    int ldrow = tid >> 2;
    int ldwd  = tid & 3;

    float acc[4][4][4];
#pragma unroll
    for (int i = 0; i < 4; i++)
#pragma unroll
        for (int j = 0; j < 4; j++)
#pragma unroll
            for (int r = 0; r < 4; r++) acc[i][j][r] = 0.0f;

    auto issue = [&](int c) {
        int s = c >> 3;
        int ko = (c & 7) * 32;
        const __half* Wp = Wsp[s];
        uint32_t sa = a_sm + (uint32_t)((c % 3) * STAGE_ELE) * 2;
        uint32_t sb = b_sm + (uint32_t)((c % 3) * STAGE_ELE) * 2;
#pragma unroll
        for (int t = 0; t < 2; t++) {
            int row = ldrow + t * 64;
            CP16(sa + (uint32_t)(row * AST + ldwd * 8) * 2,
                 Am + (mbase + row) * CC + ko + ldwd * 8);
            CP16(sb + (uint32_t)(row * AST + ldwd * 8) * 2,
                 Wp + (size_t)(nbase + row) * CC + ko + ldwd * 8);
        }
        CPCOMMIT();
    };

    int arow = (lane & 7) + 8 * ((lane >> 3) & 1);
    int akw  = (lane >> 4) * 8;
    int brow = (lane & 7) + 8 * ((lane >> 4) & 1);
    int bkw  = ((lane >> 3) & 1) * 8;

    auto compute = [&](int stage) {
        uint32_t sa = a_sm + (uint32_t)(stage * STAGE_ELE) * 2;
        uint32_t sb = b_sm + (uint32_t)(stage * STAGE_ELE) * 2;
#pragma unroll
        for (int ks = 0; ks < 32; ks += 16) {
            uint32_t afr[4][4];
#pragma unroll
            for (int mt = 0; mt < 4; mt++)
                ldsm_x4(afr[mt], sa + (uint32_t)(((wr * 64 + mt * 16 + arow) * AST) + ks + akw) * 2);
            uint32_t bfr[2][4];
#pragma unroll
            for (int nt2 = 0; nt2 < 2; nt2++)
                ldsm_x4(bfr[nt2], sb + (uint32_t)(((wc * 32 + nt2 * 16 + brow) * AST) + ks + bkw) * 2);
#pragma unroll
            for (int mt = 0; mt < 4; mt++)
#pragma unroll
                for (int nt = 0; nt < 4; nt++)
                    mma_fp16(acc[mt][nt], afr[mt],
                             bfr[nt >> 1][(nt & 1) * 2],
                             bfr[nt >> 1][(nt & 1) * 2 + 1]);
        }
    };

    issue(0);
    issue(1);
#pragma unroll 1
    for (int c = 0; c < 16; c++) {
        if (c < 14) { CPWAIT(1); } else { CPWAIT(0); }
        __syncthreads();
        if (c + 2 < 16) issue(c + 2);
        compute(c % 3);
    }

    int g = lane >> 2, ti = lane & 3;
#pragma unroll
    for (int mt = 0; mt < 4; mt++) {
#pragma unroll
        for (int nt = 0; nt < 4; nt++) {
            size_t row = mbase + wr * 64 + mt * 16 + g;
            int col = nbase + wc * 32 + nt * 8 + ti * 2;
            if (Cout) {
                float bx = 0.0f, by = 0.0f;
                if (bias) { bx = bias[col]; by = bias[col + 1]; }
                float2 v0, v1;
                v0.x = acc[mt][nt][0] + bx; v0.y = acc[mt][nt][1] + by;
                v1.x = acc[mt][nt][2] + bx; v1.y = acc[mt][nt][3] + by;
                *(float2*)&Cout[row * CC + col] = v0;
                *(float2*)&Cout[(row + 8) * CC + col] = v1;
            } else {
                uint32_t h0, l0, h1, l1;
                pack_split(acc[mt][nt][0], acc[mt][nt][1], h0, l0);
                pack_split(acc[mt][nt][2], acc[mt][nt][3], h1, l1);
                *(uint32_t*)&Ohi[row * CC + col] = h0;
                *(uint32_t*)&Olo[row * CC + col] = l0;
                *(uint32_t*)&Ohi[(row + 8) * CC + col] = h1;
                *(uint32_t*)&Olo[(row + 8) * CC + col] = l1;
            }
        }
    }
}

// ---------------- tensor-core attention: 2 CTAs/SM, bias reloaded per head ----------------
#define ATT_BUF_BYTES 19456
#define ATT_SMEM_BYTES (2 * ATT_BUF_BYTES)
__global__ __launch_bounds__(256, 2) void attn_tc_kernel() {
    extern __shared__ __nv_bfloat16 smn[];
    uint32_t sb = smem_u32(smn);
    int tid = threadIdx.x, lane = tid & 31, w = tid >> 5;
    size_t tok0 = (size_t)blockIdx.x * 128;
    int b = blockIdx.x >> 7;
    int r = lane >> 2, c = lane & 3;
    size_t trow0 = tok0 + (size_t)w * 16 + r;
    size_t trow1 = trow0 + 8;

    const uint32_t KHI = 0, KLO = 5120, VHI = 10240, VLO = 14848;

    auto issue_head = [&](int h) {
        uint32_t bo = (uint32_t)(h & 1) * ATT_BUF_BYTES;
        {
            int rr = tid >> 2, cc = tid & 3;
            size_t src = ((size_t)(b * HH + h) * KK + rr) * DD + cc * 8;
            uint32_t d = (uint32_t)(rr * 40 + cc * 8) * 2;
            CP16(sb + bo + KHI + d, g_kchi + src);
            CP16(sb + bo + KLO + d, g_kclo + src);
        }
        {
            int rr = tid >> 3, cc = tid & 7;
            size_t src = ((size_t)(b * HH + h) * DD + rr) * KK + cc * 8;
            uint32_t d = (uint32_t)(rr * 72 + cc * 8) * 2;
            CP16(sb + bo + VHI + d, g_vcThi + src);
            CP16(sb + bo + VLO + d, g_vcTlo + src);
        }
        CPCOMMIT();
    };
    issue_head(0);

    int brow = (lane & 7) + 8 * ((lane >> 4) & 1);
    int bkw  = ((lane >> 3) & 1) * 8;

#pragma unroll 1
    for (int h = 0; h < HH; h++) {
        CPWAIT(0);
        __syncthreads();
        if (h + 1 < HH) issue_head(h + 1);
        uint32_t bo = (uint32_t)(h & 1) * ATT_BUF_BYTES;

        uint32_t qhi[2][4], qlo[2][4];
#pragma unroll
        for (int ks = 0; ks < 2; ks++) {
            size_t col = (size_t)h * DD + ks * 16 + c * 2;
            qhi[ks][0] = *(const uint32_t*)(g_qhi + trow0 * CC + col);
            qhi[ks][1] = *(const uint32_t*)(g_qhi + trow1 * CC + col);
            qhi[ks][2] = *(const uint32_t*)(g_qhi + trow0 * CC + col + 8);
            qhi[ks][3] = *(const uint32_t*)(g_qhi + trow1 * CC + col + 8);
            qlo[ks][0] = *(const uint32_t*)(g_qlo + trow0 * CC + col);
            qlo[ks][1] = *(const uint32_t*)(g_qlo + trow1 * CC + col);
            qlo[ks][2] = *(const uint32_t*)(g_qlo + trow0 * CC + col + 8);
            qlo[ks][3] = *(const uint32_t*)(g_qlo + trow1 * CC + col + 8);
        }

        // logits init with bias rows (L2-resident after head 0)
        float L[8][4];
#pragma unroll
        for (int t = 0; t < 8; t++) {
            float2 b0 = *(const float2*)(g_bias + trow0 * KK + t * 8 + c * 2);
            float2 b1 = *(const float2*)(g_bias + trow1 * KK + t * 8 + c * 2);
            L[t][0] = b0.x; L[t][1] = b0.y;
            L[t][2] = b1.x; L[t][3] = b1.y;
        }
#pragma unroll
        for (int g2 = 0; g2 < 4; g2++) {
#pragma unroll
            for (int ks = 0; ks < 2; ks++) {
                uint32_t bh[4], bl[4];
                uint32_t ad = (uint32_t)((g2 * 16 + brow) * 40 + ks * 16 + bkw) * 2;
                ldsm_x4(bh, sb + bo + KHI + ad);
                ldsm_x4(bl, sb + bo + KLO + ad);
                mma_bf16(L[2*g2],   qhi[ks], bh[0], bh[1]);
                mma_bf16(L[2*g2],   qhi[ks], bl[0], bl[1]);
                mma_bf16(L[2*g2],   qlo[ks], bh[0], bh[1]);
                mma_bf16(L[2*g2+1], qhi[ks], bh[2], bh[3]);
                mma_bf16(L[2*g2+1], qhi[ks], bl[2], bl[3]);
                mma_bf16(L[2*g2+1], qlo[ks], bh[2], bh[3]);
            }
        }

        float m0 = -1e30f, m1 = -1e30f;
#pragma unroll
        for (int t = 0; t < 8; t++) {
            m0 = fmaxf(m0, fmaxf(L[t][0], L[t][1]));
            m1 = fmaxf(m1, fmaxf(L[t][2], L[t][3]));
        }
        m0 = fmaxf(m0, __shfl_xor_sync(0xffffffffu, m0, 1));
        m0 = fmaxf(m0, __shfl_xor_sync(0xffffffffu, m0, 2));
        m1 = fmaxf(m1, __shfl_xor_sync(0xffffffffu, m1, 1));
        m1 = fmaxf(m1, __shfl_xor_sync(0xffffffffu, m1, 2));
        float s0 = 0.0f, s1 = 0.0f;
#pragma unroll
        for (int t = 0; t < 8; t++) {
            L[t][0] = __expf(L[t][0] - m0); s0 += L[t][0];
            L[t][1] = __expf(L[t][1] - m0); s0 += L[t][1];
            L[t][2] = __expf(L[t][2] - m1); s1 += L[t][2];
            L[t][3] = __expf(L[t][3] - m1); s1 += L[t][3];
        }
        s0 += __shfl_xor_sync(0xffffffffu, s0, 1);
        s0 += __shfl_xor_sync(0xffffffffu, s0, 2);
        s1 += __shfl_xor_sync(0xffffffffu, s1, 1);
        s1 += __shfl_xor_sync(0xffffffffu, s1, 2);
        float inv0 = 1.0f / s0, inv1 = 1.0f / s1;

        float O[4][4];
#pragma unroll
        for (int t = 0; t < 4; t++)
#pragma unroll
            for (int v = 0; v < 4; v++) O[t][v] = 0.0f;
#pragma unroll
        for (int kc_ = 0; kc_ < 4; kc_++) {
            uint32_t ahi[4], alo[4];
            pack_split(L[2*kc_][0]*inv0,   L[2*kc_][1]*inv0,   ahi[0], alo[0]);
            pack_split(L[2*kc_][2]*inv1,   L[2*kc_][3]*inv1,   ahi[1], alo[1]);
            pack_split(L[2*kc_+1][0]*inv0, L[2*kc_+1][1]*inv0, ahi[2], alo[2]);
            pack_split(L[2*kc_+1][2]*inv1, L[2*kc_+1][3]*inv1, ahi[3], alo[3]);
#pragma unroll
            for (int g2 = 0; g2 < 2; g2++) {
                uint32_t bh[4], bl[4];
                uint32_t ad = (uint32_t)((g2 * 16 + brow) * 72 + kc_ * 16 + bkw) * 2;
                ldsm_x4(bh, sb + bo + VHI + ad);
                ldsm_x4(bl, sb + bo + VLO + ad);
                mma_bf16(O[2*g2],   ahi, bh[0], bh[1]);
                mma_bf16(O[2*g2],   ahi, bl[0], bl[1]);
                mma_bf16(O[2*g2],   alo, bh[0], bh[1]);
                mma_bf16(O[2*g2+1], ahi, bh[2], bh[3]);
                mma_bf16(O[2*g2+1], ahi, bl[2], bl[3]);
                mma_bf16(O[2*g2+1], alo, bh[2], bh[3]);
            }
        }

#pragma unroll
        for (int nt = 0; nt < 4; nt++) {
            size_t col = (size_t)h * DD + nt * 8 + c * 2;
            __half2 v0; v0.x = __float2half_rn(O[nt][0]); v0.y = __float2half_rn(O[nt][1]);
            __half2 v1; v1.x = __float2half_rn(O[nt][2]); v1.y = __float2half_rn(O[nt][3]);
            *(__half2*)&g_xh[trow0 * CC + col] = v0;
            *(__half2*)&g_xh[trow1 * CC + col] = v1;
        }
    }
}

// ---------------- launcher (gemm_q is my launch #4 -> ncu capture slot) ----------------
extern "C" void kernel_launch(void* const* d_in, const int* in_sizes, int n_in,
                              void* d_out, int out_size) {
    const float* X     = (const float*)d_in[0];
    const float* Ag    = (const float*)d_in[1];
    const float* wqkv  = (const float*)d_in[2];
    const float* wproj = (const float*)d_in[3];
    const float* bproj = (const float*)d_in[4];
    const float* cb    = (const float*)d_in[5];
    float* out = (float*)d_out;

    __half *pXh, *pxh, *pWqh, *pWql, *pWph, *pWpl;
    __nv_bfloat16 *pqhi, *pqlo;
    cudaGetSymbolAddress((void**)&pXh, g_Xh);
    cudaGetSymbolAddress((void**)&pxh, g_xh);
    cudaGetSymbolAddress((void**)&pWqh, g_Wqt_hi);
    cudaGetSymbolAddress((void**)&pWql, g_Wqt_lo);
    cudaGetSymbolAddress((void**)&pWph, g_Wpt_hi);
    cudaGetSymbolAddress((void**)&pWpl, g_Wpt_lo);
    cudaGetSymbolAddress((void**)&pqhi, g_qhi);
    cudaGetSymbolAddress((void**)&pqlo, g_qlo);

    cudaFuncSetAttribute(gemm_fp16x2_mma,
                         cudaFuncAttributeMaxDynamicSharedMemorySize, GEMM_SMEM_BYTES);
    cudaFuncSetAttribute(pool_tc_kernel,
                         cudaFuncAttributeMaxDynamicSharedMemorySize, POOL_SMEM);
    cudaFuncSetAttribute(attn_tc_kernel,
                         cudaFuncAttributeMaxDynamicSharedMemorySize, ATT_SMEM_BYTES);

    zero_kernel<<<(BB*KK*CC + 255) / 256, 256>>>();
    convertX_kernel<<<(BNTOT*CC) / (256*8), 256>>>(X);
    prepW_kernel<<<CC, 256>>>(wqkv, wproj);
    {   // my launch #4 -> should land in the ncu capture window
        dim3 grid(BNTOT / 128, CC / 128);
        gemm_fp16x2_mma<<<grid, 256, GEMM_SMEM_BYTES>>>(pXh, pWqh, pWql,
                                                        nullptr, nullptr, pqhi, pqlo);
    }
    convertA_kernel<<<(BNTOT*KK) / (256*8), 256>>>(Ag);  // includes fused denom
    bias_kernel<<<BNTOT / 256, 256>>>(Ag, cb);
    pool_tc_kernel<<<BB * 32, 256, POOL_SMEM>>>();
    kcvc_kernel<<<BB * KK, 256>>>(wqkv);
    attn_tc_kernel<<<BNTOT / 128, 256, ATT_SMEM_BYTES>>>();
    {
        dim3 grid(BNTOT / 128, CC / 128);
        gemm_fp16x2_mma<<<grid, 256, GEMM_SMEM_BYTES>>>(pxh, pWph, pWpl,
                                                        bproj, out, nullptr, nullptr);
    }
}

// round 11
// speedup vs baseline: 1.4189x; 1.0039x over previous
#include <cuda_runtime.h>
#include <cuda_bf16.h>
#include <cuda_fp16.h>
#include <cstdint>
#include <math.h>

#define BB 4
#define NN 16384
#define CC 256
#define HH 8
#define KK 64
#define DD 32
#define BNTOT (BB*NN)

// ---------------- scratch ----------------
__device__ float g_S[BB*KK*CC];
__device__ float g_denom[BB*KK];
__device__ float g_bias[BNTOT*KK];
__device__ __half g_Xh[BNTOT*CC], g_Xl[BNTOT*CC];
__device__ __half g_Ah[BNTOT*KK];
__device__ __half g_xh[BNTOT*CC];
__device__ __half g_Wqt_hi[CC*CC], g_Wqt_lo[CC*CC];
__device__ __half g_Wpt_hi[CC*CC], g_Wpt_lo[CC*CC];
__device__ __nv_bfloat16 g_qhi[BNTOT*CC], g_qlo[BNTOT*CC];
__device__ __nv_bfloat16 g_kchi[BB*HH*KK*DD], g_kclo[BB*HH*KK*DD];
__device__ __nv_bfloat16 g_vcThi[BB*HH*DD*KK], g_vcTlo[BB*HH*DD*KK];

// ---------------- helpers ----------------
__device__ __forceinline__ uint32_t smem_u32(const void* p) {
    uint32_t a;
    asm("{ .reg .u64 t; cvta.to.shared.u64 t, %1; cvt.u32.u64 %0, t; }" : "=r"(a) : "l"(p));
    return a;
}
#define CP16(dst, src) \
    asm volatile("cp.async.cg.shared.global [%0], [%1], 16;" :: "r"(dst), "l"(src))
#define CPCOMMIT() asm volatile("cp.async.commit_group;" ::: "memory")
#define CPWAIT(n)  asm volatile("cp.async.wait_group %0;" :: "n"(n) : "memory")

__device__ __forceinline__ void ldsm_x4(uint32_t* r, uint32_t addr) {
    asm volatile("ldmatrix.sync.aligned.m8n8.x4.shared.b16 {%0,%1,%2,%3}, [%4];"
                 : "=r"(r[0]), "=r"(r[1]), "=r"(r[2]), "=r"(r[3]) : "r"(addr));
}
__device__ __forceinline__ void ldsm_x4_t(uint32_t* r, uint32_t addr) {
    asm volatile("ldmatrix.sync.aligned.m8n8.x4.trans.shared.b16 {%0,%1,%2,%3}, [%4];"
                 : "=r"(r[0]), "=r"(r[1]), "=r"(r[2]), "=r"(r[3]) : "r"(addr));
}
__device__ __forceinline__ void mma_bf16(float* d, const uint32_t* a,
                                         uint32_t b0, uint32_t b1) {
    asm volatile(
        "mma.sync.aligned.m16n8k16.row.col.f32.bf16.bf16.f32 "
        "{%0,%1,%2,%3}, {%4,%5,%6,%7}, {%8,%9}, {%0,%1,%2,%3};"
        : "+f"(d[0]), "+f"(d[1]), "+f"(d[2]), "+f"(d[3])
        : "r"(a[0]), "r"(a[1]), "r"(a[2]), "r"(a[3]), "r"(b0), "r"(b1));
}
__device__ __forceinline__ void mma_fp16(float* d, const uint32_t* a,
                                         uint32_t b0, uint32_t b1) {
    asm volatile(
        "mma.sync.aligned.m16n8k16.row.col.f32.f16.f16.f32 "
        "{%0,%1,%2,%3}, {%4,%5,%6,%7}, {%8,%9}, {%0,%1,%2,%3};"
        : "+f"(d[0]), "+f"(d[1]), "+f"(d[2]), "+f"(d[3])
        : "r"(a[0]), "r"(a[1]), "r"(a[2]), "r"(a[3]), "r"(b0), "r"(b1));
}
__device__ __forceinline__ void pack_split(float a, float b, uint32_t& hi, uint32_t& lo) {
    __nv_bfloat16 ah = __float2bfloat16(a), bh = __float2bfloat16(b);
    __nv_bfloat16 al = __float2bfloat16(a - __bfloat162float(ah));
    __nv_bfloat16 bl = __float2bfloat16(b - __bfloat162float(bh));
    __nv_bfloat162 hp; hp.x = ah; hp.y = bh;
    __nv_bfloat162 lp; lp.x = al; lp.y = bl;
    hi = *(uint32_t*)&hp; lo = *(uint32_t*)&lp;
}

// ---------------- zero accumulators ----------------
__global__ void zero_kernel() {
    int i = blockIdx.x * blockDim.x + threadIdx.x;
    if (i < BB*KK*CC) g_S[i] = 0.0f;
    if (i < BB*KK)    g_denom[i] = 0.0f;
}

// ---------------- fp16 splits ----------------
__global__ __launch_bounds__(256) void convertX_kernel(const float* __restrict__ X) {
    size_t i = ((size_t)blockIdx.x * 256 + threadIdx.x) * 8;
    float4 a = *(const float4*)(X + i);
    float4 b = *(const float4*)(X + i + 4);
    float v[8] = {a.x, a.y, a.z, a.w, b.x, b.y, b.z, b.w};
    __half h[8], l[8];
#pragma unroll
    for (int j = 0; j < 8; j++) {
        h[j] = __float2half_rn(v[j]);
        l[j] = __float2half_rn(v[j] - __half2float(h[j]));
    }
    *(uint4*)&g_Xh[i] = *(const uint4*)h;
    *(uint4*)&g_Xl[i] = *(const uint4*)l;
}

// convertA + fused denom (column sums of A)
__global__ __launch_bounds__(256) void convertA_kernel(const float* __restrict__ Ag) {
    __shared__ float dsum[KK];
    int tid = threadIdx.x, lane = tid & 31;
    if (tid < KK) dsum[tid] = 0.0f;
    __syncthreads();
    size_t i = ((size_t)blockIdx.x * 256 + tid) * 8;
    float4 a = *(const float4*)(Ag + i);
    float4 b = *(const float4*)(Ag + i + 4);
    float v[8] = {a.x, a.y, a.z, a.w, b.x, b.y, b.z, b.w};
    __half h[8];
#pragma unroll
    for (int j = 0; j < 8; j++) h[j] = __float2half_rn(v[j]);
    *(uint4*)&g_Ah[i] = *(const uint4*)h;
#pragma unroll
    for (int j = 0; j < 8; j++) {
        v[j] += __shfl_down_sync(0xffffffffu, v[j], 16);
        v[j] += __shfl_down_sync(0xffffffffu, v[j], 8);
    }
    if (lane < 8) {
        int k0 = (tid & 7) * 8;
#pragma unroll
        for (int j = 0; j < 8; j++) atomicAdd(&dsum[k0 + j], v[j]);
    }
    __syncthreads();
    int b_ = blockIdx.x >> 9;
    if (tid < KK) atomicAdd(&g_denom[b_ * KK + tid], dsum[tid]);
}

// ---------------- transposed fp16 hi/lo weights ----------------
__global__ __launch_bounds__(256) void prepW_kernel(const float* __restrict__ wqkv,
                                                    const float* __restrict__ wproj) {
    int n = blockIdx.x, k = threadIdx.x;
    float wq = wqkv[k * (3*CC) + n];
    float wp = wproj[k * CC + n];
    __half qh = __float2half_rn(wq);
    __half ph = __float2half_rn(wp);
    int o = n * CC + k;
    g_Wqt_hi[o] = qh;
    g_Wqt_lo[o] = __float2half_rn(wq - __half2float(qh));
    g_Wpt_hi[o] = ph;
    g_Wpt_lo[o] = __float2half_rn(wp - __half2float(ph));
}

// ---------------- bias = A @ cluster_bias ----------------
__global__ __launch_bounds__(256) void bias_kernel(const float* __restrict__ Ag,
                                                   const float* __restrict__ cb) {
    __shared__ float cb_s[KK*KK];
    int tid = threadIdx.x;
    {
        const float4* cb4 = (const float4*)cb;
        float4* cbs4 = (float4*)cb_s;
        for (int i = tid; i < KK*KK/4; i += 256) cbs4[i] = cb4[i];
    }
    __syncthreads();
    size_t n = (size_t)blockIdx.x * 256 + tid;
    float biasr[64];
#pragma unroll
    for (int l = 0; l < 64; l++) biasr[l] = 0.0f;
    const float4* arow = (const float4*)(Ag + n * KK);
#pragma unroll
    for (int k4 = 0; k4 < 16; k4++) {
        float4 a4 = arow[k4];
        float avv[4] = {a4.x, a4.y, a4.z, a4.w};
#pragma unroll
        for (int kk = 0; kk < 4; kk++) {
            const float4* cbr = (const float4*)(cb_s + (k4 * 4 + kk) * 64);
#pragma unroll
            for (int l4 = 0; l4 < 16; l4++) {
                float4 c4 = cbr[l4];
                biasr[l4*4+0] += avv[kk] * c4.x;
                biasr[l4*4+1] += avv[kk] * c4.y;
                biasr[l4*4+2] += avv[kk] * c4.z;
                biasr[l4*4+3] += avv[kk] * c4.w;
            }
        }
    }
    float4* dst = (float4*)(g_bias + n * KK);
#pragma unroll
    for (int l4 = 0; l4 < 16; l4++)
        dst[l4] = make_float4(biasr[l4*4], biasr[l4*4+1], biasr[l4*4+2], biasr[l4*4+3]);
}

// ---------------- tensor-core pooling (unchanged from R10) ----------------
#define PX_ST 264
#define PA_ST 72
#define PX_SIZE (64*PX_ST)
#define PA_SIZE (64*PA_ST)
#define POOL_SMEM ((3*PX_SIZE + 3*PA_SIZE)*2)
__global__ __launch_bounds__(256, 1) void pool_tc_kernel() {
    extern __shared__ __half ps[];
    uint32_t sb = smem_u32(ps);
    int tid = threadIdx.x, lane = tid & 31, w = tid >> 5;
    int wm = w >> 2, wn = w & 3;
    int b = blockIdx.x >> 5;
    int nbase = (blockIdx.x & 31) * 512;
    const __half* Asrc[2] = {g_Ah, g_Ah};
    const __half* Xsrc[2] = {g_Xh, g_Xl};

    float acc[2][8][4];
#pragma unroll
    for (int i = 0; i < 2; i++)
#pragma unroll
        for (int j = 0; j < 8; j++)
#pragma unroll
            for (int r = 0; r < 4; r++) acc[i][j][r] = 0.0f;

    auto issue = [&](int c) {
        int s = c >> 3, kc_ = c & 7, buf = c % 3;
        size_t grow0 = (size_t)b * NN + nbase + kc_ * 64;
#pragma unroll
        for (int i = 0; i < 8; i++) {
            int idx = tid + i * 256;
            int row = idx >> 5, ch = idx & 31;
            CP16(sb + (uint32_t)(buf * PX_SIZE + row * PX_ST + ch * 8) * 2,
                 Xsrc[s] + (grow0 + row) * CC + ch * 8);
        }
#pragma unroll
        for (int i = 0; i < 2; i++) {
            int idx = tid + i * 256;
            int row = idx >> 3, ch = idx & 7;
            CP16(sb + (uint32_t)(3 * PX_SIZE + buf * PA_SIZE + row * PA_ST + ch * 8) * 2,
                 Asrc[s] + (grow0 + row) * KK + ch * 8);
        }
        CPCOMMIT();
    };

    issue(0); issue(1);
#pragma unroll 1
    for (int c = 0; c < 16; c++) {
        if (c < 14) { CPWAIT(1); } else { CPWAIT(0); }
        __syncthreads();
        if (c + 2 < 16) issue(c + 2);
        int buf = c % 3;
        uint32_t xb = sb + (uint32_t)(buf * PX_SIZE) * 2;
        uint32_t ab = sb + (uint32_t)(3 * PX_SIZE + buf * PA_SIZE) * 2;
#pragma unroll
        for (int kt = 0; kt < 4; kt++) {
            uint32_t af[2][4];
#pragma unroll
            for (int mt = 0; mt < 2; mt++) {
                uint32_t r[4];
                ldsm_x4_t(r, ab + (uint32_t)((kt * 16 + (lane & 15)) * PA_ST +
                                             wm * 32 + mt * 16 + (lane >> 4) * 8) * 2);
                af[mt][0] = r[0]; af[mt][1] = r[2]; af[mt][2] = r[1]; af[mt][3] = r[3];
            }
#pragma unroll
            for (int nb = 0; nb < 4; nb++) {
                uint32_t bfr[4];
                ldsm_x4_t(bfr, xb + (uint32_t)((kt * 16 + (lane & 15)) * PX_ST +
                                               wn * 64 + nb * 16 + (lane >> 4) * 8) * 2);
#pragma unroll
                for (int mt = 0; mt < 2; mt++) {
                    mma_fp16(acc[mt][nb*2],   af[mt], bfr[0], bfr[1]);
                    mma_fp16(acc[mt][nb*2+1], af[mt], bfr[2], bfr[3]);
                }
            }
        }
    }
#pragma unroll
    for (int mt = 0; mt < 2; mt++)
#pragma unroll
        for (int nt = 0; nt < 8; nt++) {
            int cl = wm * 32 + mt * 16 + (lane >> 2);
            int col = wn * 64 + nt * 8 + 2 * (lane & 3);
            float* d0 = &g_S[(b * KK + cl) * CC + col];
            atomicAdd(d0,     acc[mt][nt][0]);
            atomicAdd(d0 + 1, acc[mt][nt][1]);
            float* d1 = &g_S[(b * KK + cl + 8) * CC + col];
            atomicAdd(d1,     acc[mt][nt][2]);
            atomicAdd(d1 + 1, acc[mt][nt][3]);
        }
}

// ---------------- kc/vc from S -> scaled bf16 splits + transposed vc ----------------
__global__ __launch_bounds__(256) void kcvc_kernel(const float* __restrict__ wqkv) {
    int bk = blockIdx.x;
    int b = bk >> 6;
    int k = bk & 63;
    int t = threadIdx.x;
    __shared__ float s_row[CC];
    s_row[t] = g_S[bk * CC + t];
    __syncthreads();
    float inv = 1.0f / (g_denom[bk] + 1e-8f);
    float ak = 0.0f, av = 0.0f;
#pragma unroll 8
    for (int c = 0; c < CC; c++) {
        float s = s_row[c];
        ak += s * wqkv[c * (3*CC) + CC  + t];
        av += s * wqkv[c * (3*CC) + 2*CC + t];
    }
    int h = t >> 5, dd = t & 31;
    const float SC = 0.17677669529663689f;
    float kcv = ak * inv * SC;
    float vcv = av * inv;
    size_t ok = ((size_t)(b * HH + h) * KK + k) * DD + dd;
    size_t ov = ((size_t)(b * HH + h) * DD + dd) * KK + k;
    __nv_bfloat16 kh = __float2bfloat16(kcv);
    __nv_bfloat16 vh = __float2bfloat16(vcv);
    g_kchi[ok] = kh;  g_kclo[ok] = __float2bfloat16(kcv - __bfloat162float(kh));
    g_vcThi[ov] = vh; g_vcTlo[ov] = __float2bfloat16(vcv - __bfloat162float(vh));
}

// ---------------- HMMA fp16 2-term GEMM: shared-A restructure ----------------
// 8 chunks of K=32 over K=256; each chunk stages {A, Whi, Wlo}, both products
// accumulate into one acc. 3 stages, 1 barrier/chunk.
#define AST 40
#define TILE_ELE (128 * AST)
#define STAGE_ELE (3 * TILE_ELE)
#define GEMM_SMEM_BYTES (3 * STAGE_ELE * 2)   // 92160 B
__global__ __launch_bounds__(256, 2) void gemm_fp16x2_mma(
    const __half* __restrict__ Am,
    const __half* __restrict__ Whi, const __half* __restrict__ Wlo,
    const float* __restrict__ bias, float* __restrict__ Cout,
    __nv_bfloat16* __restrict__ Ohi, __nv_bfloat16* __restrict__ Olo) {
    extern __shared__ __half smemh[];
    uint32_t s_base = smem_u32(smemh);

    int tid = threadIdx.x;
    int lane = tid & 31, w = tid >> 5;
    int wr = w >> 2, wc = w & 3;
    size_t mbase = (size_t)blockIdx.x * 128;
    int nbase = blockIdx.y * 128;

    int ldrow = tid >> 1;            // 0..127
    int ldw0  = (tid & 1) * 2;       // first of 2 16B-words handled (0 or 2)

    float acc[4][4][4];
#pragma unroll
    for (int i = 0; i < 4; i++)
#pragma unroll
        for (int j = 0; j < 4; j++)
#pragma unroll
            for (int r = 0; r < 4; r++) acc[i][j][r] = 0.0f;

    auto issue = [&](int c) {
        int ko = c * 32;
        uint32_t sa = s_base + (uint32_t)((c % 3) * STAGE_ELE) * 2;
#pragma unroll
        for (int j = 0; j < 2; j++) {
            int cw = ldw0 + j;
            uint32_t d = (uint32_t)(ldrow * AST + cw * 8) * 2;
            CP16(sa + d,                       Am  + (mbase + ldrow) * CC + ko + cw * 8);
            CP16(sa + d + TILE_ELE * 2,        Whi + (size_t)(nbase + ldrow) * CC + ko + cw * 8);
            CP16(sa + d + 2 * TILE_ELE * 2,    Wlo + (size_t)(nbase + ldrow) * CC + ko + cw * 8);
        }
        CPCOMMIT();
    };

    int arow = (lane & 7) + 8 * ((lane >> 3) & 1);
    int akw  = (lane >> 4) * 8;
    int brow = (lane & 7) + 8 * ((lane >> 4) & 1);
    int bkw  = ((lane >> 3) & 1) * 8;

    auto compute = [&](int stage) {
        uint32_t sa  = s_base + (uint32_t)(stage * STAGE_ELE) * 2;
        uint32_t sbh = sa + (uint32_t)TILE_ELE * 2;
        uint32_t sbl = sa + (uint32_t)(2 * TILE_ELE) * 2;
#pragma unroll
        for (int ks = 0; ks < 32; ks += 16) {
            uint32_t afr[4][4];
#pragma unroll
            for (int mt = 0; mt < 4; mt++)
                ldsm_x4(afr[mt], sa + (uint32_t)(((wr * 64 + mt * 16 + arow) * AST) + ks + akw) * 2);
            uint32_t bh[2][4], bl[2][4];
#pragma unroll
            for (int nt2 = 0; nt2 < 2; nt2++) {
                uint32_t off = (uint32_t)(((wc * 32 + nt2 * 16 + brow) * AST) + ks + bkw) * 2;
                ldsm_x4(bh[nt2], sbh + off);
                ldsm_x4(bl[nt2], sbl + off);
            }
#pragma unroll
            for (int mt = 0; mt < 4; mt++)
#pragma unroll
                for (int nt = 0; nt < 4; nt++) {
                    mma_fp16(acc[mt][nt], afr[mt],
                             bh[nt >> 1][(nt & 1) * 2], bh[nt >> 1][(nt & 1) * 2 + 1]);
                    mma_fp16(acc[mt][nt], afr[mt],
                             bl[nt >> 1][(nt & 1) * 2], bl[nt >> 1][(nt & 1) * 2 + 1]);
                }
        }
    };

    issue(0);
    issue(1);
#pragma unroll 1
    for (int c = 0; c < 8; c++) {
        if (c < 6) { CPWAIT(1); } else { CPWAIT(0); }
        __syncthreads();
        if (c + 2 < 8) issue(c + 2);
        compute(c % 3);
    }

    int g = lane >> 2, ti = lane & 3;
#pragma unroll
    for (int mt = 0; mt < 4; mt++) {
#pragma unroll
        for (int nt = 0; nt < 4; nt++) {
            size_t row = mbase + wr * 64 + mt * 16 + g;
            int col = nbase + wc * 32 + nt * 8 + ti * 2;
            if (Cout) {
                float bx = 0.0f, by = 0.0f;
                if (bias) { bx = bias[col]; by = bias[col + 1]; }
                float2 v0, v1;
                v0.x = acc[mt][nt][0] + bx; v0.y = acc[mt][nt][1] + by;
                v1.x = acc[mt][nt][2] + bx; v1.y = acc[mt][nt][3] + by;
                *(float2*)&Cout[row * CC + col] = v0;
                *(float2*)&Cout[(row + 8) * CC + col] = v1;
            } else {
                uint32_t h0, l0, h1, l1;
                pack_split(acc[mt][nt][0], acc[mt][nt][1], h0, l0);
                pack_split(acc[mt][nt][2], acc[mt][nt][3], h1, l1);
                *(uint32_t*)&Ohi[row * CC + col] = h0;
                *(uint32_t*)&Olo[row * CC + col] = l0;
                *(uint32_t*)&Ohi[(row + 8) * CC + col] = h1;
                *(uint32_t*)&Olo[(row + 8) * CC + col] = l1;
            }
        }
    }
}

// ---------------- tensor-core attention (unchanged from R10) ----------------
#define ATT_BUF_BYTES 19456
#define ATT_SMEM_BYTES (2 * ATT_BUF_BYTES)
__global__ __launch_bounds__(256, 2) void attn_tc_kernel() {
    extern __shared__ __nv_bfloat16 smn[];
    uint32_t sb = smem_u32(smn);
    int tid = threadIdx.x, lane = tid & 31, w = tid >> 5;
    size_t tok0 = (size_t)blockIdx.x * 128;
    int b = blockIdx.x >> 7;
    int r = lane >> 2, c = lane & 3;
    size_t trow0 = tok0 + (size_t)w * 16 + r;
    size_t trow1 = trow0 + 8;

    const uint32_t KHI = 0, KLO = 5120, VHI = 10240, VLO = 14848;

    auto issue_head = [&](int h) {
        uint32_t bo = (uint32_t)(h & 1) * ATT_BUF_BYTES;
        {
            int rr = tid >> 2, cc = tid & 3;
            size_t src = ((size_t)(b * HH + h) * KK + rr) * DD + cc * 8;
            uint32_t d = (uint32_t)(rr * 40 + cc * 8) * 2;
            CP16(sb + bo + KHI + d, g_kchi + src);
            CP16(sb + bo + KLO + d, g_kclo + src);
        }
        {
            int rr = tid >> 3, cc = tid & 7;
            size_t src = ((size_t)(b * HH + h) * DD + rr) * KK + cc * 8;
            uint32_t d = (uint32_t)(rr * 72 + cc * 8) * 2;
            CP16(sb + bo + VHI + d, g_vcThi + src);
            CP16(sb + bo + VLO + d, g_vcTlo + src);
        }
        CPCOMMIT();
    };
    issue_head(0);

    int brow = (lane & 7) + 8 * ((lane >> 4) & 1);
    int bkw  = ((lane >> 3) & 1) * 8;

#pragma unroll 1
    for (int h = 0; h < HH; h++) {
        CPWAIT(0);
        __syncthreads();
        if (h + 1 < HH) issue_head(h + 1);
        uint32_t bo = (uint32_t)(h & 1) * ATT_BUF_BYTES;

        uint32_t qhi[2][4], qlo[2][4];
#pragma unroll
        for (int ks = 0; ks < 2; ks++) {
            size_t col = (size_t)h * DD + ks * 16 + c * 2;
            qhi[ks][0] = *(const uint32_t*)(g_qhi + trow0 * CC + col);
            qhi[ks][1] = *(const uint32_t*)(g_qhi + trow1 * CC + col);
            qhi[ks][2] = *(const uint32_t*)(g_qhi + trow0 * CC + col + 8);
            qhi[ks][3] = *(const uint32_t*)(g_qhi + trow1 * CC + col + 8);
            qlo[ks][0] = *(const uint32_t*)(g_qlo + trow0 * CC + col);
            qlo[ks][1] = *(const uint32_t*)(g_qlo + trow1 * CC + col);
            qlo[ks][2] = *(const uint32_t*)(g_qlo + trow0 * CC + col + 8);
            qlo[ks][3] = *(const uint32_t*)(g_qlo + trow1 * CC + col + 8);
        }

        float L[8][4];
#pragma unroll
        for (int t = 0; t < 8; t++) {
            float2 b0 = *(const float2*)(g_bias + trow0 * KK + t * 8 + c * 2);
            float2 b1 = *(const float2*)(g_bias + trow1 * KK + t * 8 + c * 2);
            L[t][0] = b0.x; L[t][1] = b0.y;
            L[t][2] = b1.x; L[t][3] = b1.y;
        }
#pragma unroll
        for (int g2 = 0; g2 < 4; g2++) {
#pragma unroll
            for (int ks = 0; ks < 2; ks++) {
                uint32_t bh[4], bl[4];
                uint32_t ad = (uint32_t)((g2 * 16 + brow) * 40 + ks * 16 + bkw) * 2;
                ldsm_x4(bh, sb + bo + KHI + ad);
                ldsm_x4(bl, sb + bo + KLO + ad);
                mma_bf16(L[2*g2],   qhi[ks], bh[0], bh[1]);
                mma_bf16(L[2*g2],   qhi[ks], bl[0], bl[1]);
                mma_bf16(L[2*g2],   qlo[ks], bh[0], bh[1]);
                mma_bf16(L[2*g2+1], qhi[ks], bh[2], bh[3]);
                mma_bf16(L[2*g2+1], qhi[ks], bl[2], bl[3]);
                mma_bf16(L[2*g2+1], qlo[ks], bh[2], bh[3]);
            }
        }

        float m0 = -1e30f, m1 = -1e30f;
#pragma unroll
        for (int t = 0; t < 8; t++) {
            m0 = fmaxf(m0, fmaxf(L[t][0], L[t][1]));
            m1 = fmaxf(m1, fmaxf(L[t][2], L[t][3]));
        }
        m0 = fmaxf(m0, __shfl_xor_sync(0xffffffffu, m0, 1));
        m0 = fmaxf(m0, __shfl_xor_sync(0xffffffffu, m0, 2));
        m1 = fmaxf(m1, __shfl_xor_sync(0xffffffffu, m1, 1));
        m1 = fmaxf(m1, __shfl_xor_sync(0xffffffffu, m1, 2));
        float s0 = 0.0f, s1 = 0.0f;
#pragma unroll
        for (int t = 0; t < 8; t++) {
            L[t][0] = __expf(L[t][0] - m0); s0 += L[t][0];
            L[t][1] = __expf(L[t][1] - m0); s0 += L[t][1];
            L[t][2] = __expf(L[t][2] - m1); s1 += L[t][2];
            L[t][3] = __expf(L[t][3] - m1); s1 += L[t][3];
        }
        s0 += __shfl_xor_sync(0xffffffffu, s0, 1);
        s0 += __shfl_xor_sync(0xffffffffu, s0, 2);
        s1 += __shfl_xor_sync(0xffffffffu, s1, 1);
        s1 += __shfl_xor_sync(0xffffffffu, s1, 2);
        float inv0 = 1.0f / s0, inv1 = 1.0f / s1;

        float O[4][4];
#pragma unroll
        for (int t = 0; t < 4; t++)
#pragma unroll
            for (int v = 0; v < 4; v++) O[t][v] = 0.0f;
#pragma unroll
        for (int kc_ = 0; kc_ < 4; kc_++) {
            uint32_t ahi[4], alo[4];
            pack_split(L[2*kc_][0]*inv0,   L[2*kc_][1]*inv0,   ahi[0], alo[0]);
            pack_split(L[2*kc_][2]*inv1,   L[2*kc_][3]*inv1,   ahi[1], alo[1]);
            pack_split(L[2*kc_+1][0]*inv0, L[2*kc_+1][1]*inv0, ahi[2], alo[2]);
            pack_split(L[2*kc_+1][2]*inv1, L[2*kc_+1][3]*inv1, ahi[3], alo[3]);
#pragma unroll
            for (int g2 = 0; g2 < 2; g2++) {
                uint32_t bh[4], bl[4];
                uint32_t ad = (uint32_t)((g2 * 16 + brow) * 72 + kc_ * 16 + bkw) * 2;
                ldsm_x4(bh, sb + bo + VHI + ad);
                ldsm_x4(bl, sb + bo + VLO + ad);
                mma_bf16(O[2*g2],   ahi, bh[0], bh[1]);
                mma_bf16(O[2*g2],   ahi, bl[0], bl[1]);
                mma_bf16(O[2*g2],   alo, bh[0], bh[1]);
                mma_bf16(O[2*g2+1], ahi, bh[2], bh[3]);
                mma_bf16(O[2*g2+1], ahi, bl[2], bl[3]);
                mma_bf16(O[2*g2+1], alo, bh[2], bh[3]);
            }
        }

#pragma unroll
        for (int nt = 0; nt < 4; nt++) {
            size_t col = (size_t)h * DD + nt * 8 + c * 2;
            __half2 v0; v0.x = __float2half_rn(O[nt][0]); v0.y = __float2half_rn(O[nt][1]);
            __half2 v1; v1.x = __float2half_rn(O[nt][2]); v1.y = __float2half_rn(O[nt][3]);
            *(__half2*)&g_xh[trow0 * CC + col] = v0;
            *(__half2*)&g_xh[trow1 * CC + col] = v1;
        }
    }
}

// ---------------- launcher (gemm_q at launch #4 -> ncu capture slot) ----------------
extern "C" void kernel_launch(void* const* d_in, const int* in_sizes, int n_in,
                              void* d_out, int out_size) {
    const float* X     = (const float*)d_in[0];
    const float* Ag    = (const float*)d_in[1];
    const float* wqkv  = (const float*)d_in[2];
    const float* wproj = (const float*)d_in[3];
    const float* bproj = (const float*)d_in[4];
    const float* cb    = (const float*)d_in[5];
    float* out = (float*)d_out;

    __half *pXh, *pxh, *pWqh, *pWql, *pWph, *pWpl;
    __nv_bfloat16 *pqhi, *pqlo;
    cudaGetSymbolAddress((void**)&pXh, g_Xh);
    cudaGetSymbolAddress((void**)&pxh, g_xh);
    cudaGetSymbolAddress((void**)&pWqh, g_Wqt_hi);
    cudaGetSymbolAddress((void**)&pWql, g_Wqt_lo);
    cudaGetSymbolAddress((void**)&pWph, g_Wpt_hi);
    cudaGetSymbolAddress((void**)&pWpl, g_Wpt_lo);
    cudaGetSymbolAddress((void**)&pqhi, g_qhi);
    cudaGetSymbolAddress((void**)&pqlo, g_qlo);

    cudaFuncSetAttribute(gemm_fp16x2_mma,
                         cudaFuncAttributeMaxDynamicSharedMemorySize, GEMM_SMEM_BYTES);
    cudaFuncSetAttribute(pool_tc_kernel,
                         cudaFuncAttributeMaxDynamicSharedMemorySize, POOL_SMEM);
    cudaFuncSetAttribute(attn_tc_kernel,
                         cudaFuncAttributeMaxDynamicSharedMemorySize, ATT_SMEM_BYTES);

    zero_kernel<<<(BB*KK*CC + 255) / 256, 256>>>();
    convertX_kernel<<<(BNTOT*CC) / (256*8), 256>>>(X);
    prepW_kernel<<<CC, 256>>>(wqkv, wproj);
    {   // launch #4 -> ncu capture window
        dim3 grid(BNTOT / 128, CC / 128);
        gemm_fp16x2_mma<<<grid, 256, GEMM_SMEM_BYTES>>>(pXh, pWqh, pWql,
                                                        nullptr, nullptr, pqhi, pqlo);
    }
    convertA_kernel<<<(BNTOT*KK) / (256*8), 256>>>(Ag);
    bias_kernel<<<BNTOT / 256, 256>>>(Ag, cb);
    pool_tc_kernel<<<BB * 32, 256, POOL_SMEM>>>();
    kcvc_kernel<<<BB * KK, 256>>>(wqkv);
    attn_tc_kernel<<<BNTOT / 128, 256, ATT_SMEM_BYTES>>>();
    {
        dim3 grid(BNTOT / 128, CC / 128);
        gemm_fp16x2_mma<<<grid, 256, GEMM_SMEM_BYTES>>>(pxh, pWph, pWpl,
                                                        bproj, out, nullptr, nullptr);
    }
}

// round 12
// speedup vs baseline: 1.4412x; 1.0157x over previous
#include <cuda_runtime.h>
#include <cuda_bf16.h>
#include <cuda_fp16.h>
#include <cstdint>
#include <math.h>

#define BB 4
#define NN 16384
#define CC 256
#define HH 8
#define KK 64
#define DD 32
#define BNTOT (BB*NN)

// ---------------- scratch ----------------
__device__ float g_S[BB*KK*CC];
__device__ float g_denom[BB*KK];
__device__ float g_bias[BNTOT*KK];
__device__ __half g_Xh[BNTOT*CC], g_Xl[BNTOT*CC];
__device__ __half g_Ah[BNTOT*KK];
__device__ __half g_xh[BNTOT*CC];                            // PLANAR [h][n][32] fp16
__device__ __half g_Wqt_hi[CC*CC], g_Wqt_lo[CC*CC];
__device__ __half g_Wpt_hi[CC*CC], g_Wpt_lo[CC*CC];
__device__ __nv_bfloat16 g_qhi[BNTOT*CC], g_qlo[BNTOT*CC];   // PLANAR [h][n][32] bf16
__device__ __nv_bfloat16 g_kchi[BB*HH*KK*DD], g_kclo[BB*HH*KK*DD];
__device__ __nv_bfloat16 g_vcThi[BB*HH*DD*KK], g_vcTlo[BB*HH*DD*KK];

// ---------------- helpers ----------------
__device__ __forceinline__ uint32_t smem_u32(const void* p) {
    uint32_t a;
    asm("{ .reg .u64 t; cvta.to.shared.u64 t, %1; cvt.u32.u64 %0, t; }" : "=r"(a) : "l"(p));
    return a;
}
#define CP16(dst, src) \
    asm volatile("cp.async.cg.shared.global [%0], [%1], 16;" :: "r"(dst), "l"(src))
#define CPCOMMIT() asm volatile("cp.async.commit_group;" ::: "memory")
#define CPWAIT(n)  asm volatile("cp.async.wait_group %0;" :: "n"(n) : "memory")

__device__ __forceinline__ void ldsm_x4(uint32_t* r, uint32_t addr) {
    asm volatile("ldmatrix.sync.aligned.m8n8.x4.shared.b16 {%0,%1,%2,%3}, [%4];"
                 : "=r"(r[0]), "=r"(r[1]), "=r"(r[2]), "=r"(r[3]) : "r"(addr));
}
__device__ __forceinline__ void ldsm_x4_t(uint32_t* r, uint32_t addr) {
    asm volatile("ldmatrix.sync.aligned.m8n8.x4.trans.shared.b16 {%0,%1,%2,%3}, [%4];"
                 : "=r"(r[0]), "=r"(r[1]), "=r"(r[2]), "=r"(r[3]) : "r"(addr));
}
__device__ __forceinline__ void mma_bf16(float* d, const uint32_t* a,
                                         uint32_t b0, uint32_t b1) {
    asm volatile(
        "mma.sync.aligned.m16n8k16.row.col.f32.bf16.bf16.f32 "
        "{%0,%1,%2,%3}, {%4,%5,%6,%7}, {%8,%9}, {%0,%1,%2,%3};"
        : "+f"(d[0]), "+f"(d[1]), "+f"(d[2]), "+f"(d[3])
        : "r"(a[0]), "r"(a[1]), "r"(a[2]), "r"(a[3]), "r"(b0), "r"(b1));
}
__device__ __forceinline__ void mma_fp16(float* d, const uint32_t* a,
                                         uint32_t b0, uint32_t b1) {
    asm volatile(
        "mma.sync.aligned.m16n8k16.row.col.f32.f16.f16.f32 "
        "{%0,%1,%2,%3}, {%4,%5,%6,%7}, {%8,%9}, {%0,%1,%2,%3};"
        : "+f"(d[0]), "+f"(d[1]), "+f"(d[2]), "+f"(d[3])
        : "r"(a[0]), "r"(a[1]), "r"(a[2]), "r"(a[3]), "r"(b0), "r"(b1));
}
__device__ __forceinline__ void pack_split(float a, float b, uint32_t& hi, uint32_t& lo) {
    __nv_bfloat16 ah = __float2bfloat16(a), bh = __float2bfloat16(b);
    __nv_bfloat16 al = __float2bfloat16(a - __bfloat162float(ah));
    __nv_bfloat16 bl = __float2bfloat16(b - __bfloat162float(bh));
    __nv_bfloat162 hp; hp.x = ah; hp.y = bh;
    __nv_bfloat162 lp; lp.x = al; lp.y = bl;
    hi = *(uint32_t*)&hp; lo = *(uint32_t*)&lp;
}

// ---------------- fp16 splits ----------------
__global__ __launch_bounds__(256) void convertX_kernel(const float* __restrict__ X) {
    size_t i = ((size_t)blockIdx.x * 256 + threadIdx.x) * 8;
    float4 a = *(const float4*)(X + i);
    float4 b = *(const float4*)(X + i + 4);
    float v[8] = {a.x, a.y, a.z, a.w, b.x, b.y, b.z, b.w};
    __half h[8], l[8];
#pragma unroll
    for (int j = 0; j < 8; j++) {
        h[j] = __float2half_rn(v[j]);
        l[j] = __float2half_rn(v[j] - __half2float(h[j]));
    }
    *(uint4*)&g_Xh[i] = *(const uint4*)h;
    *(uint4*)&g_Xl[i] = *(const uint4*)l;
}

// convertA + fused denom (column sums of A)
__global__ __launch_bounds__(256) void convertA_kernel(const float* __restrict__ Ag) {
    __shared__ float dsum[KK];
    int tid = threadIdx.x, lane = tid & 31;
    if (tid < KK) dsum[tid] = 0.0f;
    __syncthreads();
    size_t i = ((size_t)blockIdx.x * 256 + tid) * 8;
    float4 a = *(const float4*)(Ag + i);
    float4 b = *(const float4*)(Ag + i + 4);
    float v[8] = {a.x, a.y, a.z, a.w, b.x, b.y, b.z, b.w};
    __half h[8];
#pragma unroll
    for (int j = 0; j < 8; j++) h[j] = __float2half_rn(v[j]);
    *(uint4*)&g_Ah[i] = *(const uint4*)h;
#pragma unroll
    for (int j = 0; j < 8; j++) {
        v[j] += __shfl_down_sync(0xffffffffu, v[j], 16);
        v[j] += __shfl_down_sync(0xffffffffu, v[j], 8);
    }
    if (lane < 8) {
        int k0 = (tid & 7) * 8;
#pragma unroll
        for (int j = 0; j < 8; j++) atomicAdd(&dsum[k0 + j], v[j]);
    }
    __syncthreads();
    int b_ = blockIdx.x >> 9;
    if (tid < KK) atomicAdd(&g_denom[b_ * KK + tid], dsum[tid]);
}

// ---------------- transposed fp16 hi/lo weights ----------------
__global__ __launch_bounds__(256) void prepW_kernel(const float* __restrict__ wqkv,
                                                    const float* __restrict__ wproj) {
    int n = blockIdx.x, k = threadIdx.x;
    float wq = wqkv[k * (3*CC) + n];
    float wp = wproj[k * CC + n];
    __half qh = __float2half_rn(wq);
    __half ph = __float2half_rn(wp);
    int o = n * CC + k;
    g_Wqt_hi[o] = qh;
    g_Wqt_lo[o] = __float2half_rn(wq - __half2float(qh));
    g_Wpt_hi[o] = ph;
    g_Wpt_lo[o] = __float2half_rn(wp - __half2float(ph));
}

// ---------------- bias = A @ cluster_bias ----------------
__global__ __launch_bounds__(256) void bias_kernel(const float* __restrict__ Ag,
                                                   const float* __restrict__ cb) {
    __shared__ float cb_s[KK*KK];
    int tid = threadIdx.x;
    {
        const float4* cb4 = (const float4*)cb;
        float4* cbs4 = (float4*)cb_s;
        for (int i = tid; i < KK*KK/4; i += 256) cbs4[i] = cb4[i];
    }
    __syncthreads();
    size_t n = (size_t)blockIdx.x * 256 + tid;
    float biasr[64];
#pragma unroll
    for (int l = 0; l < 64; l++) biasr[l] = 0.0f;
    const float4* arow = (const float4*)(Ag + n * KK);
#pragma unroll
    for (int k4 = 0; k4 < 16; k4++) {
        float4 a4 = arow[k4];
        float avv[4] = {a4.x, a4.y, a4.z, a4.w};
#pragma unroll
        for (int kk = 0; kk < 4; kk++) {
            const float4* cbr = (const float4*)(cb_s + (k4 * 4 + kk) * 64);
#pragma unroll
            for (int l4 = 0; l4 < 16; l4++) {
                float4 c4 = cbr[l4];
                biasr[l4*4+0] += avv[kk] * c4.x;
                biasr[l4*4+1] += avv[kk] * c4.y;
                biasr[l4*4+2] += avv[kk] * c4.z;
                biasr[l4*4+3] += avv[kk] * c4.w;
            }
        }
    }
    float4* dst = (float4*)(g_bias + n * KK);
#pragma unroll
    for (int l4 = 0; l4 < 16; l4++)
        dst[l4] = make_float4(biasr[l4*4], biasr[l4*4+1], biasr[l4*4+2], biasr[l4*4+3]);
}

// ---------------- tensor-core pooling (unchanged) ----------------
#define PX_ST 264
#define PA_ST 72
#define PX_SIZE (64*PX_ST)
#define PA_SIZE (64*PA_ST)
#define POOL_SMEM ((3*PX_SIZE + 3*PA_SIZE)*2)
__global__ __launch_bounds__(256, 1) void pool_tc_kernel() {
    extern __shared__ __half ps[];
    uint32_t sb = smem_u32(ps);
    int tid = threadIdx.x, lane = tid & 31, w = tid >> 5;
    int wm = w >> 2, wn = w & 3;
    int b = blockIdx.x >> 5;
    int nbase = (blockIdx.x & 31) * 512;
    const __half* Asrc[2] = {g_Ah, g_Ah};
    const __half* Xsrc[2] = {g_Xh, g_Xl};

    float acc[2][8][4];
#pragma unroll
    for (int i = 0; i < 2; i++)
#pragma unroll
        for (int j = 0; j < 8; j++)
#pragma unroll
            for (int r = 0; r < 4; r++) acc[i][j][r] = 0.0f;

    auto issue = [&](int c) {
        int s = c >> 3, kc_ = c & 7, buf = c % 3;
        size_t grow0 = (size_t)b * NN + nbase + kc_ * 64;
#pragma unroll
        for (int i = 0; i < 8; i++) {
            int idx = tid + i * 256;
            int row = idx >> 5, ch = idx & 31;
            CP16(sb + (uint32_t)(buf * PX_SIZE + row * PX_ST + ch * 8) * 2,
                 Xsrc[s] + (grow0 + row) * CC + ch * 8);
        }
#pragma unroll
        for (int i = 0; i < 2; i++) {
            int idx = tid + i * 256;
            int row = idx >> 3, ch = idx & 7;
            CP16(sb + (uint32_t)(3 * PX_SIZE + buf * PA_SIZE + row * PA_ST + ch * 8) * 2,
                 Asrc[s] + (grow0 + row) * KK + ch * 8);
        }
        CPCOMMIT();
    };

    issue(0); issue(1);
#pragma unroll 1
    for (int c = 0; c < 16; c++) {
        if (c < 14) { CPWAIT(1); } else { CPWAIT(0); }
        __syncthreads();
        if (c + 2 < 16) issue(c + 2);
        int buf = c % 3;
        uint32_t xb = sb + (uint32_t)(buf * PX_SIZE) * 2;
        uint32_t ab = sb + (uint32_t)(3 * PX_SIZE + buf * PA_SIZE) * 2;
#pragma unroll
        for (int kt = 0; kt < 4; kt++) {
            uint32_t af[2][4];
#pragma unroll
            for (int mt = 0; mt < 2; mt++) {
                uint32_t r[4];
                ldsm_x4_t(r, ab + (uint32_t)((kt * 16 + (lane & 15)) * PA_ST +
                                             wm * 32 + mt * 16 + (lane >> 4) * 8) * 2);
                af[mt][0] = r[0]; af[mt][1] = r[2]; af[mt][2] = r[1]; af[mt][3] = r[3];
            }
#pragma unroll
            for (int nb = 0; nb < 4; nb++) {
                uint32_t bfr[4];
                ldsm_x4_t(bfr, xb + (uint32_t)((kt * 16 + (lane & 15)) * PX_ST +
                                               wn * 64 + nb * 16 + (lane >> 4) * 8) * 2);
#pragma unroll
                for (int mt = 0; mt < 2; mt++) {
                    mma_fp16(acc[mt][nb*2],   af[mt], bfr[0], bfr[1]);
                    mma_fp16(acc[mt][nb*2+1], af[mt], bfr[2], bfr[3]);
                }
            }
        }
    }
#pragma unroll
    for (int mt = 0; mt < 2; mt++)
#pragma unroll
        for (int nt = 0; nt < 8; nt++) {
            int cl = wm * 32 + mt * 16 + (lane >> 2);
            int col = wn * 64 + nt * 8 + 2 * (lane & 3);
            float* d0 = &g_S[(b * KK + cl) * CC + col];
            atomicAdd(d0,     acc[mt][nt][0]);
            atomicAdd(d0 + 1, acc[mt][nt][1]);
            float* d1 = &g_S[(b * KK + cl + 8) * CC + col];
            atomicAdd(d1,     acc[mt][nt][2]);
            atomicAdd(d1 + 1, acc[mt][nt][3]);
        }
}

// ---------------- kc/vc from S -> scaled bf16 splits + transposed vc ----------------
__global__ __launch_bounds__(256) void kcvc_kernel(const float* __restrict__ wqkv) {
    int bk = blockIdx.x;
    int b = bk >> 6;
    int k = bk & 63;
    int t = threadIdx.x;
    __shared__ float s_row[CC];
    s_row[t] = g_S[bk * CC + t];
    __syncthreads();
    float inv = 1.0f / (g_denom[bk] + 1e-8f);
    float ak = 0.0f, av = 0.0f;
#pragma unroll 8
    for (int c = 0; c < CC; c++) {
        float s = s_row[c];
        ak += s * wqkv[c * (3*CC) + CC  + t];
        av += s * wqkv[c * (3*CC) + 2*CC + t];
    }
    int h = t >> 5, dd = t & 31;
    const float SC = 0.17677669529663689f;
    float kcv = ak * inv * SC;
    float vcv = av * inv;
    size_t ok = ((size_t)(b * HH + h) * KK + k) * DD + dd;
    size_t ov = ((size_t)(b * HH + h) * DD + dd) * KK + k;
    __nv_bfloat16 kh = __float2bfloat16(kcv);
    __nv_bfloat16 vh = __float2bfloat16(vcv);
    g_kchi[ok] = kh;  g_kclo[ok] = __float2bfloat16(kcv - __bfloat162float(kh));
    g_vcThi[ov] = vh; g_vcTlo[ov] = __float2bfloat16(vcv - __bfloat162float(vh));
}

// ---------------- HMMA fp16 2-term GEMM (shared-A, 8 chunks of K=32) ----------------
// a_planar: A stored [h][n][32] (x-gemm); chunk c == head plane c.
// Q-gemm epilogue writes bf16 splits PLANAR [h][n][32].
#define AST 40
#define TILE_ELE (128 * AST)
#define STAGE_ELE (3 * TILE_ELE)
#define GEMM_SMEM_BYTES (3 * STAGE_ELE * 2)
__global__ __launch_bounds__(256, 2) void gemm_fp16x2_mma(
    const __half* __restrict__ Am, int a_planar,
    const __half* __restrict__ Whi, const __half* __restrict__ Wlo,
    const float* __restrict__ bias, float* __restrict__ Cout,
    __nv_bfloat16* __restrict__ Ohi, __nv_bfloat16* __restrict__ Olo) {
    extern __shared__ __half smemh[];
    uint32_t s_base = smem_u32(smemh);

    int tid = threadIdx.x;
    int lane = tid & 31, w = tid >> 5;
    int wr = w >> 2, wc = w & 3;
    size_t mbase = (size_t)blockIdx.x * 128;
    int nbase = blockIdx.y * 128;

    int ldrow = tid >> 1;
    int ldw0  = (tid & 1) * 2;

    float acc[4][4][4];
#pragma unroll
    for (int i = 0; i < 4; i++)
#pragma unroll
        for (int j = 0; j < 4; j++)
#pragma unroll
            for (int r = 0; r < 4; r++) acc[i][j][r] = 0.0f;

    auto issue = [&](int c) {
        int ko = c * 32;
        uint32_t sa = s_base + (uint32_t)((c % 3) * STAGE_ELE) * 2;
        const __half* Abase = a_planar
            ? Am + ((size_t)c * BNTOT + mbase + ldrow) * 32
            : Am + (mbase + ldrow) * CC + ko;
#pragma unroll
        for (int j = 0; j < 2; j++) {
            int cw = ldw0 + j;
            uint32_t d = (uint32_t)(ldrow * AST + cw * 8) * 2;
            CP16(sa + d,                    Abase + cw * 8);
            CP16(sa + d + TILE_ELE * 2,     Whi + (size_t)(nbase + ldrow) * CC + ko + cw * 8);
            CP16(sa + d + 2 * TILE_ELE * 2, Wlo + (size_t)(nbase + ldrow) * CC + ko + cw * 8);
        }
        CPCOMMIT();
    };

    int arow = (lane & 7) + 8 * ((lane >> 3) & 1);
    int akw  = (lane >> 4) * 8;
    int brow = (lane & 7) + 8 * ((lane >> 4) & 1);
    int bkw  = ((lane >> 3) & 1) * 8;

    auto compute = [&](int stage) {
        uint32_t sa  = s_base + (uint32_t)(stage * STAGE_ELE) * 2;
        uint32_t sbh = sa + (uint32_t)TILE_ELE * 2;
        uint32_t sbl = sa + (uint32_t)(2 * TILE_ELE) * 2;
#pragma unroll
        for (int ks = 0; ks < 32; ks += 16) {
            uint32_t afr[4][4];
#pragma unroll
            for (int mt = 0; mt < 4; mt++)
                ldsm_x4(afr[mt], sa + (uint32_t)(((wr * 64 + mt * 16 + arow) * AST) + ks + akw) * 2);
            uint32_t bh[2][4], bl[2][4];
#pragma unroll
            for (int nt2 = 0; nt2 < 2; nt2++) {
                uint32_t off = (uint32_t)(((wc * 32 + nt2 * 16 + brow) * AST) + ks + bkw) * 2;
                ldsm_x4(bh[nt2], sbh + off);
                ldsm_x4(bl[nt2], sbl + off);
            }
#pragma unroll
            for (int mt = 0; mt < 4; mt++)
#pragma unroll
                for (int nt = 0; nt < 4; nt++) {
                    mma_fp16(acc[mt][nt], afr[mt],
                             bh[nt >> 1][(nt & 1) * 2], bh[nt >> 1][(nt & 1) * 2 + 1]);
                    mma_fp16(acc[mt][nt], afr[mt],
                             bl[nt >> 1][(nt & 1) * 2], bl[nt >> 1][(nt & 1) * 2 + 1]);
                }
        }
    };

    issue(0);
    issue(1);
#pragma unroll 1
    for (int c = 0; c < 8; c++) {
        if (c < 6) { CPWAIT(1); } else { CPWAIT(0); }
        __syncthreads();
        if (c + 2 < 8) issue(c + 2);
        compute(c % 3);
    }

    int g = lane >> 2, ti = lane & 3;
#pragma unroll
    for (int mt = 0; mt < 4; mt++) {
#pragma unroll
        for (int nt = 0; nt < 4; nt++) {
            size_t row = mbase + wr * 64 + mt * 16 + g;
            int col = nbase + wc * 32 + nt * 8 + ti * 2;
            if (Cout) {
                float bx = 0.0f, by = 0.0f;
                if (bias) { bx = bias[col]; by = bias[col + 1]; }
                float2 v0, v1;
                v0.x = acc[mt][nt][0] + bx; v0.y = acc[mt][nt][1] + by;
                v1.x = acc[mt][nt][2] + bx; v1.y = acc[mt][nt][3] + by;
                *(float2*)&Cout[row * CC + col] = v0;
                *(float2*)&Cout[(row + 8) * CC + col] = v1;
            } else {
                // planar [h][n][32]: h = col>>5, d = col&31
                int hh = col >> 5, dd0 = col & 31;
                size_t o0 = ((size_t)hh * BNTOT + row) * 32 + dd0;
                size_t o1 = ((size_t)hh * BNTOT + row + 8) * 32 + dd0;
                uint32_t h0, l0, h1, l1;
                pack_split(acc[mt][nt][0], acc[mt][nt][1], h0, l0);
                pack_split(acc[mt][nt][2], acc[mt][nt][3], h1, l1);
                *(uint32_t*)&Ohi[o0] = h0;
                *(uint32_t*)&Olo[o0] = l0;
                *(uint32_t*)&Ohi[o1] = h1;
                *(uint32_t*)&Olo[o1] = l1;
            }
        }
    }
}

// ---------------- tensor-core attention (planar Q/x IO) ----------------
#define ATT_BUF_BYTES 19456
#define ATT_SMEM_BYTES (2 * ATT_BUF_BYTES)
__global__ __launch_bounds__(256, 2) void attn_tc_kernel() {
    extern __shared__ __nv_bfloat16 smn[];
    uint32_t sb = smem_u32(smn);
    int tid = threadIdx.x, lane = tid & 31, w = tid >> 5;
    size_t tok0 = (size_t)blockIdx.x * 128;
    int b = blockIdx.x >> 7;
    int r = lane >> 2, c = lane & 3;
    size_t trow0 = tok0 + (size_t)w * 16 + r;
    size_t trow1 = trow0 + 8;

    const uint32_t KHI = 0, KLO = 5120, VHI = 10240, VLO = 14848;

    auto issue_head = [&](int h) {
        uint32_t bo = (uint32_t)(h & 1) * ATT_BUF_BYTES;
        {
            int rr = tid >> 2, cc = tid & 3;
            size_t src = ((size_t)(b * HH + h) * KK + rr) * DD + cc * 8;
            uint32_t d = (uint32_t)(rr * 40 + cc * 8) * 2;
            CP16(sb + bo + KHI + d, g_kchi + src);
            CP16(sb + bo + KLO + d, g_kclo + src);
        }
        {
            int rr = tid >> 3, cc = tid & 7;
            size_t src = ((size_t)(b * HH + h) * DD + rr) * KK + cc * 8;
            uint32_t d = (uint32_t)(rr * 72 + cc * 8) * 2;
            CP16(sb + bo + VHI + d, g_vcThi + src);
            CP16(sb + bo + VLO + d, g_vcTlo + src);
        }
        CPCOMMIT();
    };
    issue_head(0);

    int brow = (lane & 7) + 8 * ((lane >> 4) & 1);
    int bkw  = ((lane >> 3) & 1) * 8;

#pragma unroll 1
    for (int h = 0; h < HH; h++) {
        CPWAIT(0);
        __syncthreads();
        if (h + 1 < HH) issue_head(h + 1);
        uint32_t bo = (uint32_t)(h & 1) * ATT_BUF_BYTES;

        // Q fragments from PLANAR layout [h][n][32] — coalesced
        const __nv_bfloat16* qh_base = g_qhi + (size_t)h * BNTOT * 32;
        const __nv_bfloat16* ql_base = g_qlo + (size_t)h * BNTOT * 32;
        uint32_t qhi[2][4], qlo[2][4];
#pragma unroll
        for (int ks = 0; ks < 2; ks++) {
            int col = ks * 16 + c * 2;
            qhi[ks][0] = *(const uint32_t*)(qh_base + trow0 * 32 + col);
            qhi[ks][1] = *(const uint32_t*)(qh_base + trow1 * 32 + col);
            qhi[ks][2] = *(const uint32_t*)(qh_base + trow0 * 32 + col + 8);
            qhi[ks][3] = *(const uint32_t*)(qh_base + trow1 * 32 + col + 8);
            qlo[ks][0] = *(const uint32_t*)(ql_base + trow0 * 32 + col);
            qlo[ks][1] = *(const uint32_t*)(ql_base + trow1 * 32 + col);
            qlo[ks][2] = *(const uint32_t*)(ql_base + trow0 * 32 + col + 8);
            qlo[ks][3] = *(const uint32_t*)(ql_base + trow1 * 32 + col + 8);
        }

        float L[8][4];
#pragma unroll
        for (int t = 0; t < 8; t++) {
            float2 b0 = *(const float2*)(g_bias + trow0 * KK + t * 8 + c * 2);
            float2 b1 = *(const float2*)(g_bias + trow1 * KK + t * 8 + c * 2);
            L[t][0] = b0.x; L[t][1] = b0.y;
            L[t][2] = b1.x; L[t][3] = b1.y;
        }
#pragma unroll
        for (int g2 = 0; g2 < 4; g2++) {
#pragma unroll
            for (int ks = 0; ks < 2; ks++) {
                uint32_t bh[4], bl[4];
                uint32_t ad = (uint32_t)((g2 * 16 + brow) * 40 + ks * 16 + bkw) * 2;
                ldsm_x4(bh, sb + bo + KHI + ad);
                ldsm_x4(bl, sb + bo + KLO + ad);
                mma_bf16(L[2*g2],   qhi[ks], bh[0], bh[1]);
                mma_bf16(L[2*g2],   qhi[ks], bl[0], bl[1]);
                mma_bf16(L[2*g2],   qlo[ks], bh[0], bh[1]);
                mma_bf16(L[2*g2+1], qhi[ks], bh[2], bh[3]);
                mma_bf16(L[2*g2+1], qhi[ks], bl[2], bl[3]);
                mma_bf16(L[2*g2+1], qlo[ks], bh[2], bh[3]);
            }
        }

        float m0 = -1e30f, m1 = -1e30f;
#pragma unroll
        for (int t = 0; t < 8; t++) {
            m0 = fmaxf(m0, fmaxf(L[t][0], L[t][1]));
            m1 = fmaxf(m1, fmaxf(L[t][2], L[t][3]));
        }
        m0 = fmaxf(m0, __shfl_xor_sync(0xffffffffu, m0, 1));
        m0 = fmaxf(m0, __shfl_xor_sync(0xffffffffu, m0, 2));
        m1 = fmaxf(m1, __shfl_xor_sync(0xffffffffu, m1, 1));
        m1 = fmaxf(m1, __shfl_xor_sync(0xffffffffu, m1, 2));
        float s0 = 0.0f, s1 = 0.0f;
#pragma unroll
        for (int t = 0; t < 8; t++) {
            L[t][0] = __expf(L[t][0] - m0); s0 += L[t][0];
            L[t][1] = __expf(L[t][1] - m0); s0 += L[t][1];
            L[t][2] = __expf(L[t][2] - m1); s1 += L[t][2];
            L[t][3] = __expf(L[t][3] - m1); s1 += L[t][3];
        }
        s0 += __shfl_xor_sync(0xffffffffu, s0, 1);
        s0 += __shfl_xor_sync(0xffffffffu, s0, 2);
        s1 += __shfl_xor_sync(0xffffffffu, s1, 1);
        s1 += __shfl_xor_sync(0xffffffffu, s1, 2);
        float inv0 = 1.0f / s0, inv1 = 1.0f / s1;

        float O[4][4];
#pragma unroll
        for (int t = 0; t < 4; t++)
#pragma unroll
            for (int v = 0; v < 4; v++) O[t][v] = 0.0f;
#pragma unroll
        for (int kc_ = 0; kc_ < 4; kc_++) {
            uint32_t ahi[4], alo[4];
            pack_split(L[2*kc_][0]*inv0,   L[2*kc_][1]*inv0,   ahi[0], alo[0]);
            pack_split(L[2*kc_][2]*inv1,   L[2*kc_][3]*inv1,   ahi[1], alo[1]);
            pack_split(L[2*kc_+1][0]*inv0, L[2*kc_+1][1]*inv0, ahi[2], alo[2]);
            pack_split(L[2*kc_+1][2]*inv1, L[2*kc_+1][3]*inv1, ahi[3], alo[3]);
#pragma unroll
            for (int g2 = 0; g2 < 2; g2++) {
                uint32_t bh[4], bl[4];
                uint32_t ad = (uint32_t)((g2 * 16 + brow) * 72 + kc_ * 16 + bkw) * 2;
                ldsm_x4(bh, sb + bo + VHI + ad);
                ldsm_x4(bl, sb + bo + VLO + ad);
                mma_bf16(O[2*g2],   ahi, bh[0], bh[1]);
                mma_bf16(O[2*g2],   ahi, bl[0], bl[1]);
                mma_bf16(O[2*g2],   alo, bh[0], bh[1]);
                mma_bf16(O[2*g2+1], ahi, bh[2], bh[3]);
                mma_bf16(O[2*g2+1], ahi, bl[2], bl[3]);
                mma_bf16(O[2*g2+1], alo, bh[2], bh[3]);
            }
        }

        // store x PLANAR [h][n][32] fp16 — coalesced
        __half* xh_base = g_xh + (size_t)h * BNTOT * 32;
#pragma unroll
        for (int nt = 0; nt < 4; nt++) {
            int col = nt * 8 + c * 2;
            __half2 v0; v0.x = __float2half_rn(O[nt][0]); v0.y = __float2half_rn(O[nt][1]);
            __half2 v1; v1.x = __float2half_rn(O[nt][2]); v1.y = __float2half_rn(O[nt][3]);
            *(__half2*)&xh_base[trow0 * 32 + col] = v0;
            *(__half2*)&xh_base[trow1 * 32 + col] = v1;
        }
    }
}

// ---------------- launcher ----------------
extern "C" void kernel_launch(void* const* d_in, const int* in_sizes, int n_in,
                              void* d_out, int out_size) {
    const float* X     = (const float*)d_in[0];
    const float* Ag    = (const float*)d_in[1];
    const float* wqkv  = (const float*)d_in[2];
    const float* wproj = (const float*)d_in[3];
    const float* bproj = (const float*)d_in[4];
    const float* cb    = (const float*)d_in[5];
    float* out = (float*)d_out;

    __half *pXh, *pxh, *pWqh, *pWql, *pWph, *pWpl;
    __nv_bfloat16 *pqhi, *pqlo;
    float *pS, *pden;
    cudaGetSymbolAddress((void**)&pXh, g_Xh);
    cudaGetSymbolAddress((void**)&pxh, g_xh);
    cudaGetSymbolAddress((void**)&pWqh, g_Wqt_hi);
    cudaGetSymbolAddress((void**)&pWql, g_Wqt_lo);
    cudaGetSymbolAddress((void**)&pWph, g_Wpt_hi);
    cudaGetSymbolAddress((void**)&pWpl, g_Wpt_lo);
    cudaGetSymbolAddress((void**)&pqhi, g_qhi);
    cudaGetSymbolAddress((void**)&pqlo, g_qlo);
    cudaGetSymbolAddress((void**)&pS, g_S);
    cudaGetSymbolAddress((void**)&pden, g_denom);

    cudaFuncSetAttribute(gemm_fp16x2_mma,
                         cudaFuncAttributeMaxDynamicSharedMemorySize, GEMM_SMEM_BYTES);
    cudaFuncSetAttribute(pool_tc_kernel,
                         cudaFuncAttributeMaxDynamicSharedMemorySize, POOL_SMEM);
    cudaFuncSetAttribute(attn_tc_kernel,
                         cudaFuncAttributeMaxDynamicSharedMemorySize, ATT_SMEM_BYTES);

    cudaMemsetAsync(pS, 0, sizeof(float) * BB * KK * CC);
    cudaMemsetAsync(pden, 0, sizeof(float) * BB * KK);
    convertX_kernel<<<(BNTOT*CC) / (256*8), 256>>>(X);
    prepW_kernel<<<CC, 256>>>(wqkv, wproj);
    {   // Q = X @ Wq, planar bf16 split output
        dim3 grid(BNTOT / 128, CC / 128);
        gemm_fp16x2_mma<<<grid, 256, GEMM_SMEM_BYTES>>>(pXh, 0, pWqh, pWql,
                                                        nullptr, nullptr, pqhi, pqlo);
    }
    convertA_kernel<<<(BNTOT*KK) / (256*8), 256>>>(Ag);
    bias_kernel<<<BNTOT / 256, 256>>>(Ag, cb);
    pool_tc_kernel<<<BB * 32, 256, POOL_SMEM>>>();
    kcvc_kernel<<<BB * KK, 256>>>(wqkv);
    attn_tc_kernel<<<BNTOT / 128, 256, ATT_SMEM_BYTES>>>();
    {   // out = x @ Wproj + b, A planar fp16
        dim3 grid(BNTOT / 128, CC / 128);
        gemm_fp16x2_mma<<<grid, 256, GEMM_SMEM_BYTES>>>(pxh, 1, pWph, pWpl,
                                                        bproj, out, nullptr, nullptr);
    }
}

// round 13
// speedup vs baseline: 1.5480x; 1.0740x over previous
#include <cuda_runtime.h>
#include <cuda_bf16.h>
#include <cuda_fp16.h>
#include <cstdint>
#include <math.h>

#define BB 4
#define NN 16384
#define CC 256
#define HH 8
#define KK 64
#define DD 32
#define BNTOT (BB*NN)

// ---------------- scratch ----------------
__device__ float g_S[BB*KK*CC];
__device__ float g_denom[BB*KK];
__device__ float g_bias[BNTOT*KK];
__device__ __half g_Xh[BNTOT*CC], g_Xl[BNTOT*CC];
__device__ __half g_Ah[BNTOT*KK];
__device__ __half g_xh[BNTOT*CC];                 // PLANAR [h][n][32] fp16
__device__ __half g_qh[BNTOT*CC];                 // PLANAR [h][n][32] fp16 (single)
__device__ __half g_Wqt_hi[CC*CC], g_Wqt_lo[CC*CC];
__device__ __half g_Wpt_hi[CC*CC], g_Wpt_lo[CC*CC];
__device__ __half g_kchi[BB*HH*KK*DD], g_kclo[BB*HH*KK*DD];   // fp16 2-term, scaled
__device__ __half g_vcThi[BB*HH*DD*KK], g_vcTlo[BB*HH*DD*KK]; // fp16 2-term, [b][h][d][cl]

// ---------------- helpers ----------------
__device__ __forceinline__ uint32_t smem_u32(const void* p) {
    uint32_t a;
    asm("{ .reg .u64 t; cvta.to.shared.u64 t, %1; cvt.u32.u64 %0, t; }" : "=r"(a) : "l"(p));
    return a;
}
#define CP16(dst, src) \
    asm volatile("cp.async.cg.shared.global [%0], [%1], 16;" :: "r"(dst), "l"(src))
#define CPCOMMIT() asm volatile("cp.async.commit_group;" ::: "memory")
#define CPWAIT(n)  asm volatile("cp.async.wait_group %0;" :: "n"(n) : "memory")

__device__ __forceinline__ void ldsm_x4(uint32_t* r, uint32_t addr) {
    asm volatile("ldmatrix.sync.aligned.m8n8.x4.shared.b16 {%0,%1,%2,%3}, [%4];"
                 : "=r"(r[0]), "=r"(r[1]), "=r"(r[2]), "=r"(r[3]) : "r"(addr));
}
__device__ __forceinline__ void ldsm_x4_t(uint32_t* r, uint32_t addr) {
    asm volatile("ldmatrix.sync.aligned.m8n8.x4.trans.shared.b16 {%0,%1,%2,%3}, [%4];"
                 : "=r"(r[0]), "=r"(r[1]), "=r"(r[2]), "=r"(r[3]) : "r"(addr));
}
__device__ __forceinline__ void mma_fp16(float* d, const uint32_t* a,
                                         uint32_t b0, uint32_t b1) {
    asm volatile(
        "mma.sync.aligned.m16n8k16.row.col.f32.f16.f16.f32 "
        "{%0,%1,%2,%3}, {%4,%5,%6,%7}, {%8,%9}, {%0,%1,%2,%3};"
        : "+f"(d[0]), "+f"(d[1]), "+f"(d[2]), "+f"(d[3])
        : "r"(a[0]), "r"(a[1]), "r"(a[2]), "r"(a[3]), "r"(b0), "r"(b1));
}
__device__ __forceinline__ uint32_t pack_h2(float a, float b) {
    __half2 h = __floats2half2_rn(a, b);
    return *(uint32_t*)&h;
}

// ---------------- fp16 splits ----------------
__global__ __launch_bounds__(256) void convertX_kernel(const float* __restrict__ X) {
    size_t i = ((size_t)blockIdx.x * 256 + threadIdx.x) * 8;
    float4 a = *(const float4*)(X + i);
    float4 b = *(const float4*)(X + i + 4);
    float v[8] = {a.x, a.y, a.z, a.w, b.x, b.y, b.z, b.w};
    __half h[8], l[8];
#pragma unroll
    for (int j = 0; j < 8; j++) {
        h[j] = __float2half_rn(v[j]);
        l[j] = __float2half_rn(v[j] - __half2float(h[j]));
    }
    *(uint4*)&g_Xh[i] = *(const uint4*)h;
    *(uint4*)&g_Xl[i] = *(const uint4*)l;
}

// convertA + fused denom
__global__ __launch_bounds__(256) void convertA_kernel(const float* __restrict__ Ag) {
    __shared__ float dsum[KK];
    int tid = threadIdx.x, lane = tid & 31;
    if (tid < KK) dsum[tid] = 0.0f;
    __syncthreads();
    size_t i = ((size_t)blockIdx.x * 256 + tid) * 8;
    float4 a = *(const float4*)(Ag + i);
    float4 b = *(const float4*)(Ag + i + 4);
    float v[8] = {a.x, a.y, a.z, a.w, b.x, b.y, b.z, b.w};
    __half h[8];
#pragma unroll
    for (int j = 0; j < 8; j++) h[j] = __float2half_rn(v[j]);
    *(uint4*)&g_Ah[i] = *(const uint4*)h;
#pragma unroll
    for (int j = 0; j < 8; j++) {
        v[j] += __shfl_down_sync(0xffffffffu, v[j], 16);
        v[j] += __shfl_down_sync(0xffffffffu, v[j], 8);
    }
    if (lane < 8) {
        int k0 = (tid & 7) * 8;
#pragma unroll
        for (int j = 0; j < 8; j++) atomicAdd(&dsum[k0 + j], v[j]);
    }
    __syncthreads();
    int b_ = blockIdx.x >> 9;
    if (tid < KK) atomicAdd(&g_denom[b_ * KK + tid], dsum[tid]);
}

// ---------------- transposed fp16 hi/lo weights ----------------
__global__ __launch_bounds__(256) void prepW_kernel(const float* __restrict__ wqkv,
                                                    const float* __restrict__ wproj) {
    int n = blockIdx.x, k = threadIdx.x;
    float wq = wqkv[k * (3*CC) + n];
    float wp = wproj[k * CC + n];
    __half qh = __float2half_rn(wq);
    __half ph = __float2half_rn(wp);
    int o = n * CC + k;
    g_Wqt_hi[o] = qh;
    g_Wqt_lo[o] = __float2half_rn(wq - __half2float(qh));
    g_Wpt_hi[o] = ph;
    g_Wpt_lo[o] = __float2half_rn(wp - __half2float(ph));
}

// ---------------- bias = A @ cluster_bias ----------------
__global__ __launch_bounds__(256) void bias_kernel(const float* __restrict__ Ag,
                                                   const float* __restrict__ cb) {
    __shared__ float cb_s[KK*KK];
    int tid = threadIdx.x;
    {
        const float4* cb4 = (const float4*)cb;
        float4* cbs4 = (float4*)cb_s;
        for (int i = tid; i < KK*KK/4; i += 256) cbs4[i] = cb4[i];
    }
    __syncthreads();
    size_t n = (size_t)blockIdx.x * 256 + tid;
    float biasr[64];
#pragma unroll
    for (int l = 0; l < 64; l++) biasr[l] = 0.0f;
    const float4* arow = (const float4*)(Ag + n * KK);
#pragma unroll
    for (int k4 = 0; k4 < 16; k4++) {
        float4 a4 = arow[k4];
        float avv[4] = {a4.x, a4.y, a4.z, a4.w};
#pragma unroll
        for (int kk = 0; kk < 4; kk++) {
            const float4* cbr = (const float4*)(cb_s + (k4 * 4 + kk) * 64);
#pragma unroll
            for (int l4 = 0; l4 < 16; l4++) {
                float4 c4 = cbr[l4];
                biasr[l4*4+0] += avv[kk] * c4.x;
                biasr[l4*4+1] += avv[kk] * c4.y;
                biasr[l4*4+2] += avv[kk] * c4.z;
                biasr[l4*4+3] += avv[kk] * c4.w;
            }
        }
    }
    float4* dst = (float4*)(g_bias + n * KK);
#pragma unroll
    for (int l4 = 0; l4 < 16; l4++)
        dst[l4] = make_float4(biasr[l4*4], biasr[l4*4+1], biasr[l4*4+2], biasr[l4*4+3]);
}

// ---------------- tensor-core pooling (unchanged) ----------------
#define PX_ST 264
#define PA_ST 72
#define PX_SIZE (64*PX_ST)
#define PA_SIZE (64*PA_ST)
#define POOL_SMEM ((3*PX_SIZE + 3*PA_SIZE)*2)
__global__ __launch_bounds__(256, 1) void pool_tc_kernel() {
    extern __shared__ __half ps[];
    uint32_t sb = smem_u32(ps);
    int tid = threadIdx.x, lane = tid & 31, w = tid >> 5;
    int wm = w >> 2, wn = w & 3;
    int b = blockIdx.x >> 5;
    int nbase = (blockIdx.x & 31) * 512;
    const __half* Asrc[2] = {g_Ah, g_Ah};
    const __half* Xsrc[2] = {g_Xh, g_Xl};

    float acc[2][8][4];
#pragma unroll
    for (int i = 0; i < 2; i++)
#pragma unroll
        for (int j = 0; j < 8; j++)
#pragma unroll
            for (int r = 0; r < 4; r++) acc[i][j][r] = 0.0f;

    auto issue = [&](int c) {
        int s = c >> 3, kc_ = c & 7, buf = c % 3;
        size_t grow0 = (size_t)b * NN + nbase + kc_ * 64;
#pragma unroll
        for (int i = 0; i < 8; i++) {
            int idx = tid + i * 256;
            int row = idx >> 5, ch = idx & 31;
            CP16(sb + (uint32_t)(buf * PX_SIZE + row * PX_ST + ch * 8) * 2,
                 Xsrc[s] + (grow0 + row) * CC + ch * 8);
        }
#pragma unroll
        for (int i = 0; i < 2; i++) {
            int idx = tid + i * 256;
            int row = idx >> 3, ch = idx & 7;
            CP16(sb + (uint32_t)(3 * PX_SIZE + buf * PA_SIZE + row * PA_ST + ch * 8) * 2,
                 Asrc[s] + (grow0 + row) * KK + ch * 8);
        }
        CPCOMMIT();
    };

    issue(0); issue(1);
#pragma unroll 1
    for (int c = 0; c < 16; c++) {
        if (c < 14) { CPWAIT(1); } else { CPWAIT(0); }
        __syncthreads();
        if (c + 2 < 16) issue(c + 2);
        int buf = c % 3;
        uint32_t xb = sb + (uint32_t)(buf * PX_SIZE) * 2;
        uint32_t ab = sb + (uint32_t)(3 * PX_SIZE + buf * PA_SIZE) * 2;
#pragma unroll
        for (int kt = 0; kt < 4; kt++) {
            uint32_t af[2][4];
#pragma unroll
            for (int mt = 0; mt < 2; mt++) {
                uint32_t r[4];
                ldsm_x4_t(r, ab + (uint32_t)((kt * 16 + (lane & 15)) * PA_ST +
                                             wm * 32 + mt * 16 + (lane >> 4) * 8) * 2);
                af[mt][0] = r[0]; af[mt][1] = r[2]; af[mt][2] = r[1]; af[mt][3] = r[3];
            }
#pragma unroll
            for (int nb = 0; nb < 4; nb++) {
                uint32_t bfr[4];
                ldsm_x4_t(bfr, xb + (uint32_t)((kt * 16 + (lane & 15)) * PX_ST +
                                               wn * 64 + nb * 16 + (lane >> 4) * 8) * 2);
#pragma unroll
                for (int mt = 0; mt < 2; mt++) {
                    mma_fp16(acc[mt][nb*2],   af[mt], bfr[0], bfr[1]);
                    mma_fp16(acc[mt][nb*2+1], af[mt], bfr[2], bfr[3]);
                }
            }
        }
    }
#pragma unroll
    for (int mt = 0; mt < 2; mt++)
#pragma unroll
        for (int nt = 0; nt < 8; nt++) {
            int cl = wm * 32 + mt * 16 + (lane >> 2);
            int col = wn * 64 + nt * 8 + 2 * (lane & 3);
            float* d0 = &g_S[(b * KK + cl) * CC + col];
            atomicAdd(d0,     acc[mt][nt][0]);
            atomicAdd(d0 + 1, acc[mt][nt][1]);
            float* d1 = &g_S[(b * KK + cl + 8) * CC + col];
            atomicAdd(d1,     acc[mt][nt][2]);
            atomicAdd(d1 + 1, acc[mt][nt][3]);
        }
}

// ---------------- kc/vc from S -> scaled fp16 2-term splits ----------------
__global__ __launch_bounds__(256) void kcvc_kernel(const float* __restrict__ wqkv) {
    int bk = blockIdx.x;
    int b = bk >> 6;
    int k = bk & 63;
    int t = threadIdx.x;
    __shared__ float s_row[CC];
    s_row[t] = g_S[bk * CC + t];
    __syncthreads();
    float inv = 1.0f / (g_denom[bk] + 1e-8f);
    float ak = 0.0f, av = 0.0f;
#pragma unroll 8
    for (int c = 0; c < CC; c++) {
        float s = s_row[c];
        ak += s * wqkv[c * (3*CC) + CC  + t];
        av += s * wqkv[c * (3*CC) + 2*CC + t];
    }
    int h = t >> 5, dd = t & 31;
    const float SC = 0.17677669529663689f;
    float kcv = ak * inv * SC;
    float vcv = av * inv;
    size_t ok = ((size_t)(b * HH + h) * KK + k) * DD + dd;
    size_t ov = ((size_t)(b * HH + h) * DD + dd) * KK + k;
    __half kh = __float2half_rn(kcv);
    __half vh = __float2half_rn(vcv);
    g_kchi[ok] = kh;  g_kclo[ok] = __float2half_rn(kcv - __half2float(kh));
    g_vcThi[ov] = vh; g_vcTlo[ov] = __float2half_rn(vcv - __half2float(vh));
}

// ---------------- HMMA fp16 2-term GEMM (shared-A, 8 chunks of K=32) ----------------
#define AST 40
#define TILE_ELE (128 * AST)
#define STAGE_ELE (3 * TILE_ELE)
#define GEMM_SMEM_BYTES (3 * STAGE_ELE * 2)
__global__ __launch_bounds__(256, 2) void gemm_fp16x2_mma(
    const __half* __restrict__ Am, int a_planar,
    const __half* __restrict__ Whi, const __half* __restrict__ Wlo,
    const float* __restrict__ bias, float* __restrict__ Cout,
    __half* __restrict__ Oh) {
    extern __shared__ __half smemh[];
    uint32_t s_base = smem_u32(smemh);

    int tid = threadIdx.x;
    int lane = tid & 31, w = tid >> 5;
    int wr = w >> 2, wc = w & 3;
    size_t mbase = (size_t)blockIdx.x * 128;
    int nbase = blockIdx.y * 128;

    int ldrow = tid >> 1;
    int ldw0  = (tid & 1) * 2;

    float acc[4][4][4];
#pragma unroll
    for (int i = 0; i < 4; i++)
#pragma unroll
        for (int j = 0; j < 4; j++)
#pragma unroll
            for (int r = 0; r < 4; r++) acc[i][j][r] = 0.0f;

    auto issue = [&](int c) {
        int ko = c * 32;
        uint32_t sa = s_base + (uint32_t)((c % 3) * STAGE_ELE) * 2;
        const __half* Abase = a_planar
            ? Am + ((size_t)c * BNTOT + mbase + ldrow) * 32
            : Am + (mbase + ldrow) * CC + ko;
#pragma unroll
        for (int j = 0; j < 2; j++) {
            int cw = ldw0 + j;
            uint32_t d = (uint32_t)(ldrow * AST + cw * 8) * 2;
            CP16(sa + d,                    Abase + cw * 8);
            CP16(sa + d + TILE_ELE * 2,     Whi + (size_t)(nbase + ldrow) * CC + ko + cw * 8);
            CP16(sa + d + 2 * TILE_ELE * 2, Wlo + (size_t)(nbase + ldrow) * CC + ko + cw * 8);
        }
        CPCOMMIT();
    };

    int arow = (lane & 7) + 8 * ((lane >> 3) & 1);
    int akw  = (lane >> 4) * 8;
    int brow = (lane & 7) + 8 * ((lane >> 4) & 1);
    int bkw  = ((lane >> 3) & 1) * 8;

    auto compute = [&](int stage) {
        uint32_t sa  = s_base + (uint32_t)(stage * STAGE_ELE) * 2;
        uint32_t sbh = sa + (uint32_t)TILE_ELE * 2;
        uint32_t sbl = sa + (uint32_t)(2 * TILE_ELE) * 2;
#pragma unroll
        for (int ks = 0; ks < 32; ks += 16) {
            uint32_t afr[4][4];
#pragma unroll
            for (int mt = 0; mt < 4; mt++)
                ldsm_x4(afr[mt], sa + (uint32_t)(((wr * 64 + mt * 16 + arow) * AST) + ks + akw) * 2);
            uint32_t bh[2][4], bl[2][4];
#pragma unroll
            for (int nt2 = 0; nt2 < 2; nt2++) {
                uint32_t off = (uint32_t)(((wc * 32 + nt2 * 16 + brow) * AST) + ks + bkw) * 2;
                ldsm_x4(bh[nt2], sbh + off);
                ldsm_x4(bl[nt2], sbl + off);
            }
#pragma unroll
            for (int mt = 0; mt < 4; mt++)
#pragma unroll
                for (int nt = 0; nt < 4; nt++) {
                    mma_fp16(acc[mt][nt], afr[mt],
                             bh[nt >> 1][(nt & 1) * 2], bh[nt >> 1][(nt & 1) * 2 + 1]);
                    mma_fp16(acc[mt][nt], afr[mt],
                             bl[nt >> 1][(nt & 1) * 2], bl[nt >> 1][(nt & 1) * 2 + 1]);
                }
        }
    };

    issue(0);
    issue(1);
#pragma unroll 1
    for (int c = 0; c < 8; c++) {
        if (c < 6) { CPWAIT(1); } else { CPWAIT(0); }
        __syncthreads();
        if (c + 2 < 8) issue(c + 2);
        compute(c % 3);
    }

    int g = lane >> 2, ti = lane & 3;
#pragma unroll
    for (int mt = 0; mt < 4; mt++) {
#pragma unroll
        for (int nt = 0; nt < 4; nt++) {
            size_t row = mbase + wr * 64 + mt * 16 + g;
            int col = nbase + wc * 32 + nt * 8 + ti * 2;
            if (Cout) {
                float bx = 0.0f, by = 0.0f;
                if (bias) { bx = bias[col]; by = bias[col + 1]; }
                float2 v0, v1;
                v0.x = acc[mt][nt][0] + bx; v0.y = acc[mt][nt][1] + by;
                v1.x = acc[mt][nt][2] + bx; v1.y = acc[mt][nt][3] + by;
                *(float2*)&Cout[row * CC + col] = v0;
                *(float2*)&Cout[(row + 8) * CC + col] = v1;
            } else {
                // single fp16 planar [h][n][32]
                int hh = col >> 5, dd0 = col & 31;
                size_t o0 = ((size_t)hh * BNTOT + row) * 32 + dd0;
                size_t o1 = ((size_t)hh * BNTOT + row + 8) * 32 + dd0;
                *(uint32_t*)&Oh[o0] = pack_h2(acc[mt][nt][0], acc[mt][nt][1]);
                *(uint32_t*)&Oh[o1] = pack_h2(acc[mt][nt][2], acc[mt][nt][3]);
            }
        }
    }
}

// ---------------- tensor-core attention: all-fp16 datapath ----------------
#define ATT_BUF_BYTES 19456
#define ATT_SMEM_BYTES (2 * ATT_BUF_BYTES)
__global__ __launch_bounds__(256, 2) void attn_tc_kernel() {
    extern __shared__ __half smn[];
    uint32_t sb = smem_u32(smn);
    int tid = threadIdx.x, lane = tid & 31, w = tid >> 5;
    size_t tok0 = (size_t)blockIdx.x * 128;
    int b = blockIdx.x >> 7;
    int r = lane >> 2, c = lane & 3;
    size_t trow0 = tok0 + (size_t)w * 16 + r;
    size_t trow1 = trow0 + 8;

    const uint32_t KHI = 0, KLO = 5120, VHI = 10240, VLO = 14848;

    auto issue_head = [&](int h) {
        uint32_t bo = (uint32_t)(h & 1) * ATT_BUF_BYTES;
        {
            int rr = tid >> 2, cc = tid & 3;
            size_t src = ((size_t)(b * HH + h) * KK + rr) * DD + cc * 8;
            uint32_t d = (uint32_t)(rr * 40 + cc * 8) * 2;
            CP16(sb + bo + KHI + d, g_kchi + src);
            CP16(sb + bo + KLO + d, g_kclo + src);
        }
        {
            int rr = tid >> 3, cc = tid & 7;
            size_t src = ((size_t)(b * HH + h) * DD + rr) * KK + cc * 8;
            uint32_t d = (uint32_t)(rr * 72 + cc * 8) * 2;
            CP16(sb + bo + VHI + d, g_vcThi + src);
            CP16(sb + bo + VLO + d, g_vcTlo + src);
        }
        CPCOMMIT();
    };
    issue_head(0);

    int brow = (lane & 7) + 8 * ((lane >> 4) & 1);
    int bkw  = ((lane >> 3) & 1) * 8;

#pragma unroll 1
    for (int h = 0; h < HH; h++) {
        CPWAIT(0);
        __syncthreads();
        if (h + 1 < HH) issue_head(h + 1);
        uint32_t bo = (uint32_t)(h & 1) * ATT_BUF_BYTES;

        // Q fragments: single fp16 planar, coalesced
        const __half* q_base = g_qh + (size_t)h * BNTOT * 32;
        uint32_t q[2][4];
#pragma unroll
        for (int ks = 0; ks < 2; ks++) {
            int col = ks * 16 + c * 2;
            q[ks][0] = *(const uint32_t*)(q_base + trow0 * 32 + col);
            q[ks][1] = *(const uint32_t*)(q_base + trow1 * 32 + col);
            q[ks][2] = *(const uint32_t*)(q_base + trow0 * 32 + col + 8);
            q[ks][3] = *(const uint32_t*)(q_base + trow1 * 32 + col + 8);
        }

        float L[8][4];
#pragma unroll
        for (int t = 0; t < 8; t++) {
            float2 b0 = *(const float2*)(g_bias + trow0 * KK + t * 8 + c * 2);
            float2 b1 = *(const float2*)(g_bias + trow1 * KK + t * 8 + c * 2);
            L[t][0] = b0.x; L[t][1] = b0.y;
            L[t][2] = b1.x; L[t][3] = b1.y;
        }
#pragma unroll
        for (int g2 = 0; g2 < 4; g2++) {
#pragma unroll
            for (int ks = 0; ks < 2; ks++) {
                uint32_t bh[4], bl[4];
                uint32_t ad = (uint32_t)((g2 * 16 + brow) * 40 + ks * 16 + bkw) * 2;
                ldsm_x4(bh, sb + bo + KHI + ad);
                ldsm_x4(bl, sb + bo + KLO + ad);
                mma_fp16(L[2*g2],   q[ks], bh[0], bh[1]);
                mma_fp16(L[2*g2],   q[ks], bl[0], bl[1]);
                mma_fp16(L[2*g2+1], q[ks], bh[2], bh[3]);
                mma_fp16(L[2*g2+1], q[ks], bl[2], bl[3]);
            }
        }

        float m0 = -1e30f, m1 = -1e30f;
#pragma unroll
        for (int t = 0; t < 8; t++) {
            m0 = fmaxf(m0, fmaxf(L[t][0], L[t][1]));
            m1 = fmaxf(m1, fmaxf(L[t][2], L[t][3]));
        }
        m0 = fmaxf(m0, __shfl_xor_sync(0xffffffffu, m0, 1));
        m0 = fmaxf(m0, __shfl_xor_sync(0xffffffffu, m0, 2));
        m1 = fmaxf(m1, __shfl_xor_sync(0xffffffffu, m1, 1));
        m1 = fmaxf(m1, __shfl_xor_sync(0xffffffffu, m1, 2));
        float s0 = 0.0f, s1 = 0.0f;
#pragma unroll
        for (int t = 0; t < 8; t++) {
            L[t][0] = __expf(L[t][0] - m0); s0 += L[t][0];
            L[t][1] = __expf(L[t][1] - m0); s0 += L[t][1];
            L[t][2] = __expf(L[t][2] - m1); s1 += L[t][2];
            L[t][3] = __expf(L[t][3] - m1); s1 += L[t][3];
        }
        s0 += __shfl_xor_sync(0xffffffffu, s0, 1);
        s0 += __shfl_xor_sync(0xffffffffu, s0, 2);
        s1 += __shfl_xor_sync(0xffffffffu, s1, 1);
        s1 += __shfl_xor_sync(0xffffffffu, s1, 2);
        float inv0 = 1.0f / s0, inv1 = 1.0f / s1;

        float O[4][4];
#pragma unroll
        for (int t = 0; t < 4; t++)
#pragma unroll
            for (int v = 0; v < 4; v++) O[t][v] = 0.0f;
#pragma unroll
        for (int kc_ = 0; kc_ < 4; kc_++) {
            // P as single fp16 fragment
            uint32_t p[4];
            p[0] = pack_h2(L[2*kc_][0] * inv0,   L[2*kc_][1] * inv0);
            p[1] = pack_h2(L[2*kc_][2] * inv1,   L[2*kc_][3] * inv1);
            p[2] = pack_h2(L[2*kc_+1][0] * inv0, L[2*kc_+1][1] * inv0);
            p[3] = pack_h2(L[2*kc_+1][2] * inv1, L[2*kc_+1][3] * inv1);
#pragma unroll
            for (int g2 = 0; g2 < 2; g2++) {
                uint32_t bh[4], bl[4];
                uint32_t ad = (uint32_t)((g2 * 16 + brow) * 72 + kc_ * 16 + bkw) * 2;
                ldsm_x4(bh, sb + bo + VHI + ad);
                ldsm_x4(bl, sb + bo + VLO + ad);
                mma_fp16(O[2*g2],   p, bh[0], bh[1]);
                mma_fp16(O[2*g2],   p, bl[0], bl[1]);
                mma_fp16(O[2*g2+1], p, bh[2], bh[3]);
                mma_fp16(O[2*g2+1], p, bl[2], bl[3]);
            }
        }

        // store x planar fp16
        __half* xh_base = g_xh + (size_t)h * BNTOT * 32;
#pragma unroll
        for (int nt = 0; nt < 4; nt++) {
            int col = nt * 8 + c * 2;
            *(uint32_t*)&xh_base[trow0 * 32 + col] = pack_h2(O[nt][0], O[nt][1]);
            *(uint32_t*)&xh_base[trow1 * 32 + col] = pack_h2(O[nt][2], O[nt][3]);
        }
    }
}

// ---------------- launcher ----------------
extern "C" void kernel_launch(void* const* d_in, const int* in_sizes, int n_in,
                              void* d_out, int out_size) {
    const float* X     = (const float*)d_in[0];
    const float* Ag    = (const float*)d_in[1];
    const float* wqkv  = (const float*)d_in[2];
    const float* wproj = (const float*)d_in[3];
    const float* bproj = (const float*)d_in[4];
    const float* cb    = (const float*)d_in[5];
    float* out = (float*)d_out;

    __half *pXh, *pxh, *pqh, *pWqh, *pWql, *pWph, *pWpl;
    float *pS, *pden;
    cudaGetSymbolAddress((void**)&pXh, g_Xh);
    cudaGetSymbolAddress((void**)&pxh, g_xh);
    cudaGetSymbolAddress((void**)&pqh, g_qh);
    cudaGetSymbolAddress((void**)&pWqh, g_Wqt_hi);
    cudaGetSymbolAddress((void**)&pWql, g_Wqt_lo);
    cudaGetSymbolAddress((void**)&pWph, g_Wpt_hi);
    cudaGetSymbolAddress((void**)&pWpl, g_Wpt_lo);
    cudaGetSymbolAddress((void**)&pS, g_S);
    cudaGetSymbolAddress((void**)&pden, g_denom);

    cudaFuncSetAttribute(gemm_fp16x2_mma,
                         cudaFuncAttributeMaxDynamicSharedMemorySize, GEMM_SMEM_BYTES);
    cudaFuncSetAttribute(pool_tc_kernel,
                         cudaFuncAttributeMaxDynamicSharedMemorySize, POOL_SMEM);
    cudaFuncSetAttribute(attn_tc_kernel,
                         cudaFuncAttributeMaxDynamicSharedMemorySize, ATT_SMEM_BYTES);

    cudaMemsetAsync(pS, 0, sizeof(float) * BB * KK * CC);
    cudaMemsetAsync(pden, 0, sizeof(float) * BB * KK);
    convertX_kernel<<<(BNTOT*CC) / (256*8), 256>>>(X);
    prepW_kernel<<<CC, 256>>>(wqkv, wproj);
    {   // Q = X @ Wq, single fp16 planar output
        dim3 grid(BNTOT / 128, CC / 128);
        gemm_fp16x2_mma<<<grid, 256, GEMM_SMEM_BYTES>>>(pXh, 0, pWqh, pWql,
                                                        nullptr, nullptr, pqh);
    }
    convertA_kernel<<<(BNTOT*KK) / (256*8), 256>>>(Ag);
    bias_kernel<<<BNTOT / 256, 256>>>(Ag, cb);
    pool_tc_kernel<<<BB * 32, 256, POOL_SMEM>>>();
    kcvc_kernel<<<BB * KK, 256>>>(wqkv);
    attn_tc_kernel<<<BNTOT / 128, 256, ATT_SMEM_BYTES>>>();
    {   // out = x @ Wproj + b
        dim3 grid(BNTOT / 128, CC / 128);
        gemm_fp16x2_mma<<<grid, 256, GEMM_SMEM_BYTES>>>(pxh, 1, pWph, pWpl,
                                                        bproj, out, nullptr);
    }
}